// round 4
// baseline (speedup 1.0000x reference)
#include <cuda_runtime.h>
#include <cstdint>
#include <cstddef>

// ---------------- problem constants ----------------
#define BATCH 2
#define C_DIM 256
#define HW 96
#define PIX (HW*HW)          // 9216
#define INNER 14
#define NFEAT (INNER*18)     // 252
#define NFPAD 256            // padded feature count for tf32 GEMM
#define NTOK PIX             // 9216
#define NBLK (NTOK/128)      // 72 row/col blocks of scores
#define NTRI (NBLK*(NBLK+1)/2) // 2628 upper-triangle blocks

// ---------------- device scratch ----------------
__device__ float g_fmap [BATCH * C_DIM * PIX];
__device__ float g_xr   [BATCH * INNER * PIX];
__device__ float g_conv [3 * BATCH * INNER * PIX];
__device__ float g_feats[BATCH * NFPAD * PIX];
__device__ float g_tokT [BATCH * C_DIM * PIX];
__device__ float g_tok  [BATCH * NTOK * C_DIM];
__device__ float g_scores[(size_t)BATCH * NTOK * NTOK];
__device__ float g_att  [BATCH * NTOK * C_DIM];
__device__ float g_mx   [BATCH * NTOK];
__device__ float g_inv  [BATCH * NTOK];
__device__ float g_fusew[C_DIM * NFPAD];

// ---------------- tf32 helpers ----------------
__device__ __forceinline__ uint32_t f2tf32(float x) {
    uint32_t u;
    asm("cvt.rna.tf32.f32 %0, %1;" : "=r"(u) : "f"(x));
    return u;
}

__device__ __forceinline__ void mma8(float* c, const uint32_t* a, const uint32_t* b) {
    asm volatile(
        "mma.sync.aligned.m16n8k8.row.col.f32.tf32.tf32.f32 "
        "{%0,%1,%2,%3},{%4,%5,%6,%7},{%8,%9},{%0,%1,%2,%3};"
        : "+f"(c[0]), "+f"(c[1]), "+f"(c[2]), "+f"(c[3])
        : "r"(a[0]), "r"(a[1]), "r"(a[2]), "r"(a[3]), "r"(b[0]), "r"(b[1]));
}

// ---------------- tf32 GEMM ----------------
// C = alpha * op(A~) * op(B) [+ bias]
// A MxK row-major. TB=false: B KxN. TB=true: B NxK.
// SYM : A==B==tok, upper-triangle block decode, mirrored stores (BM==BN).
// EXPA: A-element -> exp(a - mx[row]) on load; epilogue multiplies inv[row].
// BIAS: epilogue adds bias[row].
template<int BM, int BN, int WM, int WN, bool TB, bool SYM, bool EXPA, bool BIAS>
__global__ __launch_bounds__(256, 2)
void gemm_tf32(const float* __restrict__ A, const float* __restrict__ B,
               float* __restrict__ C, int K,
               int lda, int ldb, int ldc, float alpha,
               const float* __restrict__ bias,
               const float* __restrict__ mxp, const float* __restrict__ invp,
               size_t sA, size_t sB, size_t sC)
{
    constexpr int SA = BM + 8;
    constexpr int SB = BN + 8;
    constexpr int NA = BM / 64;
    constexpr int NB = BN / 64;

    __shared__ uint32_t As[2][16 * SA];
    __shared__ uint32_t Bs[2][16 * SB];

    const int bz = blockIdx.z;
    A += (size_t)bz * sA;
    B += (size_t)bz * sB;
    C += (size_t)bz * sC;
    const float* mx  = EXPA ? mxp  + (size_t)bz * NTOK : nullptr;
    const float* inv = EXPA ? invp + (size_t)bz * NTOK : nullptr;

    int bx, by;
    if (SYM) {
        int t = blockIdx.x;
        by = 0;
        while (t >= NBLK - by) { t -= NBLK - by; by++; }
        bx = by + t;
    } else {
        bx = blockIdx.x; by = blockIdx.y;
    }
    const int row0 = by * BM;
    const int col0 = bx * BN;

    const int tid  = threadIdx.x;
    const int lane = tid & 31;
    const int wid  = tid >> 5;
    const int wm   = wid % WM;
    const int wn   = wid / WM;
    const int g    = lane >> 2;
    const int t4   = lane & 3;
    const int arow = wm * (BM / WM);
    const int bcol = wn * (BN / WN);

    float acc[2][8][4];
    #pragma unroll
    for (int mi = 0; mi < 2; mi++)
        #pragma unroll
        for (int ni = 0; ni < 8; ni++)
            #pragma unroll
            for (int v = 0; v < 4; v++) acc[mi][ni][v] = 0.f;

    float4 ra[NA], rb[NB];
    float mxr[NA > 0 ? NA : 1];
    if (EXPA) {
        #pragma unroll
        for (int u = 0; u < NA; u++) {
            int i = tid + u * 256;
            mxr[u] = mx[row0 + (i >> 2)];
        }
    }

    auto ldgA = [&](int k0) {
        #pragma unroll
        for (int u = 0; u < NA; u++) {
            int i = tid + u * 256;
            int r = i >> 2, k4 = i & 3;
            ra[u] = *(const float4*)(A + (size_t)(row0 + r) * lda + k0 + k4 * 4);
        }
    };
    auto stsA = [&](int buf) {
        #pragma unroll
        for (int u = 0; u < NA; u++) {
            int i = tid + u * 256;
            int r = i >> 2, k4 = i & 3;
            float4 v = ra[u];
            if (EXPA) {
                v.x = __expf(v.x - mxr[u]);
                v.y = __expf(v.y - mxr[u]);
                v.z = __expf(v.z - mxr[u]);
                v.w = __expf(v.w - mxr[u]);
            }
            uint32_t* p = &As[buf][(k4 * 4) * SA + r];
            p[0 * SA] = f2tf32(v.x);
            p[1 * SA] = f2tf32(v.y);
            p[2 * SA] = f2tf32(v.z);
            p[3 * SA] = f2tf32(v.w);
        }
    };
    auto ldgB = [&](int k0) {
        #pragma unroll
        for (int u = 0; u < NB; u++) {
            int i = tid + u * 256;
            if (TB) {
                int n = i >> 2, k4 = i & 3;
                rb[u] = *(const float4*)(B + (size_t)(col0 + n) * ldb + k0 + k4 * 4);
            } else {
                int k = i / (BN / 4), n4 = i % (BN / 4);
                rb[u] = *(const float4*)(B + (size_t)(k0 + k) * ldb + col0 + n4 * 4);
            }
        }
    };
    auto stsB = [&](int buf) {
        #pragma unroll
        for (int u = 0; u < NB; u++) {
            int i = tid + u * 256;
            if (TB) {
                int n = i >> 2, k4 = i & 3;
                uint32_t* p = &Bs[buf][(k4 * 4) * SB + n];
                p[0 * SB] = f2tf32(rb[u].x);
                p[1 * SB] = f2tf32(rb[u].y);
                p[2 * SB] = f2tf32(rb[u].z);
                p[3 * SB] = f2tf32(rb[u].w);
            } else {
                int k = i / (BN / 4), n4 = i % (BN / 4);
                uint4 v;
                v.x = f2tf32(rb[u].x); v.y = f2tf32(rb[u].y);
                v.z = f2tf32(rb[u].z); v.w = f2tf32(rb[u].w);
                *(uint4*)&Bs[buf][k * SB + n4 * 4] = v;
            }
        }
    };

    ldgA(0); ldgB(0);
    stsA(0); stsB(0);
    __syncthreads();

    const int KT = K / 16;
    for (int kt = 0; kt < KT; kt++) {
        int cur = kt & 1, nxt = cur ^ 1;
        if (kt + 1 < KT) { ldgA((kt + 1) * 16); ldgB((kt + 1) * 16); }

        #pragma unroll
        for (int ks = 0; ks < 2; ks++) {
            const int kb = ks * 8;
            uint32_t af[2][4], bf[8][2];
            #pragma unroll
            for (int mi = 0; mi < 2; mi++) {
                int mr = arow + mi * 16 + g;
                af[mi][0] = As[cur][(kb + t4) * SA + mr];
                af[mi][1] = As[cur][(kb + t4) * SA + mr + 8];
                af[mi][2] = As[cur][(kb + t4 + 4) * SA + mr];
                af[mi][3] = As[cur][(kb + t4 + 4) * SA + mr + 8];
            }
            #pragma unroll
            for (int ni = 0; ni < 8; ni++) {
                int nc = bcol + ni * 8 + g;
                bf[ni][0] = Bs[cur][(kb + t4) * SB + nc];
                bf[ni][1] = Bs[cur][(kb + t4 + 4) * SB + nc];
            }
            #pragma unroll
            for (int mi = 0; mi < 2; mi++)
                #pragma unroll
                for (int ni = 0; ni < 8; ni++)
                    mma8(acc[mi][ni], af[mi], bf[ni]);
        }

        if (kt + 1 < KT) { stsA(nxt); stsB(nxt); }
        __syncthreads();
    }

    #pragma unroll
    for (int mi = 0; mi < 2; mi++) {
        int r = row0 + arow + mi * 16 + g;
        float s0 = alpha, s1 = alpha;
        if (EXPA) { s0 *= inv[r]; s1 *= inv[r + 8]; }
        float b0 = 0.f, b1 = 0.f;
        if (BIAS) { b0 = bias[r]; b1 = bias[r + 8]; }
        #pragma unroll
        for (int ni = 0; ni < 8; ni++) {
            int c = col0 + bcol + ni * 8 + t4 * 2;
            float2 v0, v1;
            v0.x = s0 * acc[mi][ni][0] + b0;
            v0.y = s0 * acc[mi][ni][1] + b0;
            v1.x = s1 * acc[mi][ni][2] + b1;
            v1.y = s1 * acc[mi][ni][3] + b1;
            *(float2*)&C[(size_t)r * ldc + c]       = v0;
            *(float2*)&C[(size_t)(r + 8) * ldc + c] = v1;
            if (SYM && bx != by) {
                C[(size_t)c * ldc + r]             = v0.x;
                C[(size_t)(c + 1) * ldc + r]       = v0.y;
                C[(size_t)c * ldc + (r + 8)]       = v1.x;
                C[(size_t)(c + 1) * ldc + (r + 8)] = v1.y;
            }
        }
    }
}

// ---------------- pad fuse weights 252 -> 256 K ----------------
__global__ __launch_bounds__(256)
void copyw_kernel(const float* __restrict__ w, float* __restrict__ wp)
{
    int r = blockIdx.x;            // 0..255
    int k = threadIdx.x;           // 0..255
    wp[r * NFPAD + k] = (k < NFEAT) ? w[r * NFEAT + k] : 0.f;
}

// ---------------- reduce ----------------
__global__ __launch_bounds__(256)
void reduce_kernel(const float* __restrict__ fmap, const float* __restrict__ w,
                   const float* __restrict__ bias, float* __restrict__ xr)
{
    __shared__ float ws[INNER * C_DIM];
    int tid = threadIdx.x;
    for (int i = tid; i < INNER * C_DIM; i += 256) ws[i] = w[i];
    __syncthreads();

    int b = blockIdx.y;
    int p = blockIdx.x * 256 + tid;
    const float* fin = fmap + (size_t)b * C_DIM * PIX;
    float acc[INNER];
    #pragma unroll
    for (int o = 0; o < INNER; o++) acc[o] = 0.f;
    for (int ci = 0; ci < C_DIM; ci++) {
        float v = fin[(size_t)ci * PIX + p];
        #pragma unroll
        for (int o = 0; o < INNER; o++) acc[o] += ws[o * C_DIM + ci] * v;
    }
    float* xo = xr + (size_t)b * INNER * PIX;
    #pragma unroll
    for (int o = 0; o < INNER; o++) xo[(size_t)o * PIX + p] = acc[o] + bias[o];
}

// ---------------- dilated 3x3 conv ----------------
__global__ __launch_bounds__(256)
void dilconv_kernel(const float* __restrict__ xr, const float* __restrict__ dw,
                    const float* __restrict__ db, float* __restrict__ conv)
{
    __shared__ float ws[INNER * INNER * 9];
    int i = blockIdx.z;
    int d = i + 1;
    int b = blockIdx.y;
    int tid = threadIdx.x;
    for (int k = tid; k < INNER * INNER * 9; k += 256)
        ws[k] = dw[(size_t)i * INNER * INNER * 9 + k];
    __syncthreads();

    int p = blockIdx.x * 256 + tid;
    int h = p / HW, w = p % HW;
    const float* xin = xr + (size_t)b * INNER * PIX;
    float acc[INNER];
    #pragma unroll
    for (int co = 0; co < INNER; co++) acc[co] = 0.f;

    #pragma unroll
    for (int kh = 0; kh < 3; kh++) {
        int hh = h + (kh - 1) * d;
        if (hh < 0 || hh >= HW) continue;
        #pragma unroll
        for (int kw = 0; kw < 3; kw++) {
            int ww = w + (kw - 1) * d;
            if (ww < 0 || ww >= HW) continue;
            int q = hh * HW + ww;
            for (int ci = 0; ci < INNER; ci++) {
                float v = xin[(size_t)ci * PIX + q];
                int widx = ci * 9 + kh * 3 + kw;
                #pragma unroll
                for (int co = 0; co < INNER; co++)
                    acc[co] += ws[co * (INNER * 9) + widx] * v;
            }
        }
    }
    float* cout = conv + ((size_t)(i * BATCH + b) * INNER) * PIX;
    #pragma unroll
    for (int co = 0; co < INNER; co++)
        cout[(size_t)co * PIX + p] = acc[co] + db[i * INNER + co];
}

// ---------------- feats (+ zero padding channels) ----------------
__global__ __launch_bounds__(256)
void feats_kernel(const float* __restrict__ xr, const float* __restrict__ conv,
                  float* __restrict__ feats)
{
    int b = blockIdx.y;
    int p = blockIdx.x * 256 + threadIdx.x;
    int h = p / HW, w = p % HW;
    const float* xin = xr + (size_t)b * INNER * PIX;
    float* fo = feats + (size_t)b * NFPAD * PIX;

    int q[6];
    q[0] = p;
    q[1] = h * HW + (HW - 1 - w);
    q[2] = (HW - 1 - h) * HW + w;
    q[3] = w * HW + (HW - 1 - h);
    q[4] = (HW - 1 - h) * HW + (HW - 1 - w);
    q[5] = (HW - 1 - w) * HW + h;

    for (int c = 0; c < INNER; c++) {
        float cv[3];
        #pragma unroll
        for (int i = 0; i < 3; i++)
            cv[i] = conv[((size_t)(i * BATCH + b) * INNER + c) * PIX + p];
        float tv[6];
        #pragma unroll
        for (int t = 0; t < 6; t++)
            tv[t] = xin[(size_t)c * PIX + q[t]];
        #pragma unroll
        for (int i = 0; i < 3; i++)
            #pragma unroll
            for (int t = 0; t < 6; t++)
                fo[((size_t)((i * 6 + t) * INNER + c)) * PIX + p] = cv[i] * tv[t];
    }
    #pragma unroll
    for (int f = NFEAT; f < NFPAD; f++)
        fo[(size_t)f * PIX + p] = 0.f;
}

// ---------------- transpose ----------------
__global__ __launch_bounds__(256)
void transpose_kernel(const float* __restrict__ src, float* __restrict__ dst)
{
    __shared__ float tile[32][33];
    int b = blockIdx.z;
    int p0 = blockIdx.x * 32, c0 = blockIdx.y * 32;
    const float* s = src + (size_t)b * C_DIM * PIX;
    float* d = dst + (size_t)b * NTOK * C_DIM;
    int tx = threadIdx.x, ty = threadIdx.y;
    #pragma unroll
    for (int j = 0; j < 32; j += 8)
        tile[ty + j][tx] = s[(size_t)(c0 + ty + j) * PIX + p0 + tx];
    __syncthreads();
    #pragma unroll
    for (int j = 0; j < 32; j += 8)
        d[(size_t)(p0 + ty + j) * C_DIM + c0 + tx] = tile[tx][ty + j];
}

// ---------------- row stats: max + 1/sum(exp) ----------------
__global__ __launch_bounds__(256)
void rowstats_kernel(const float* __restrict__ S, float* __restrict__ mx,
                     float* __restrict__ inv)
{
    __shared__ float buf[NTOK];
    __shared__ float red[256];
    int n = blockIdx.x, b = blockIdx.y;
    const float* row = S + ((size_t)b * NTOK + n) * NTOK;
    int tid = threadIdx.x;

    float m = -1e30f;
    for (int i = tid; i < NTOK; i += 256) { float v = row[i]; buf[i] = v; m = fmaxf(m, v); }
    red[tid] = m; __syncthreads();
    for (int s = 128; s > 0; s >>= 1) { if (tid < s) red[tid] = fmaxf(red[tid], red[tid + s]); __syncthreads(); }
    m = red[0];
    __syncthreads();

    float sum = 0.f;
    for (int i = tid; i < NTOK; i += 256) sum += __expf(buf[i] - m);
    red[tid] = sum; __syncthreads();
    for (int s = 128; s > 0; s >>= 1) { if (tid < s) red[tid] += red[tid + s]; __syncthreads(); }

    if (tid == 0) {
        mx[(size_t)b * NTOK + n]  = m;
        inv[(size_t)b * NTOK + n] = 1.f / red[0];
    }
}

// ---------------- final ----------------
__global__ __launch_bounds__(256)
void final_kernel(const float* __restrict__ fmap, const float* __restrict__ att,
                  float* __restrict__ out)
{
    __shared__ float tile[32][33];
    int b = blockIdx.z;
    int p0 = blockIdx.x * 32, c0 = blockIdx.y * 32;
    int tx = threadIdx.x, ty = threadIdx.y;
    const float* a = att + (size_t)b * NTOK * C_DIM;
    #pragma unroll
    for (int j = 0; j < 32; j += 8)
        tile[ty + j][tx] = a[(size_t)(p0 + ty + j) * C_DIM + c0 + tx];
    __syncthreads();
    const float* f = fmap + (size_t)b * C_DIM * PIX;
    float* o = out + (size_t)b * C_DIM * PIX;
    #pragma unroll
    for (int j = 0; j < 32; j += 8) {
        int c = c0 + ty + j, p = p0 + tx;
        o[(size_t)c * PIX + p] = f[(size_t)c * PIX + p] + 0.2f * tile[tx][ty + j];
    }
}

// ---------------- launch ----------------
extern "C" void kernel_launch(void* const* d_in, const int* in_sizes, int n_in,
                              void* d_out, int out_size)
{
    const float* x        = (const float*)d_in[0];
    const float* proj_w   = (const float*)d_in[1];
    const float* proj_b   = (const float*)d_in[2];
    const float* reduce_w = (const float*)d_in[3];
    const float* reduce_b = (const float*)d_in[4];
    const float* dil_w    = (const float*)d_in[5];
    const float* dil_b    = (const float*)d_in[6];
    const float* fuse_w   = (const float*)d_in[7];
    const float* fuse_b   = (const float*)d_in[8];
    float* out = (float*)d_out;

    void *p_fmap, *p_xr, *p_conv, *p_feats, *p_tokT, *p_tok, *p_scores, *p_att,
         *p_mx, *p_inv, *p_fusew;
    cudaGetSymbolAddress(&p_fmap,   g_fmap);
    cudaGetSymbolAddress(&p_xr,     g_xr);
    cudaGetSymbolAddress(&p_conv,   g_conv);
    cudaGetSymbolAddress(&p_feats,  g_feats);
    cudaGetSymbolAddress(&p_tokT,   g_tokT);
    cudaGetSymbolAddress(&p_tok,    g_tok);
    cudaGetSymbolAddress(&p_scores, g_scores);
    cudaGetSymbolAddress(&p_att,    g_att);
    cudaGetSymbolAddress(&p_mx,     g_mx);
    cudaGetSymbolAddress(&p_inv,    g_inv);
    cudaGetSymbolAddress(&p_fusew,  g_fusew);

    float* fmap   = (float*)p_fmap;
    float* xr     = (float*)p_xr;
    float* conv   = (float*)p_conv;
    float* feats  = (float*)p_feats;
    float* tokT   = (float*)p_tokT;
    float* tok    = (float*)p_tok;
    float* scores = (float*)p_scores;
    float* att    = (float*)p_att;
    float* mx     = (float*)p_mx;
    float* inv    = (float*)p_inv;
    float* fusew  = (float*)p_fusew;

    // 0) pad fuse weights
    copyw_kernel<<<C_DIM, 256>>>(fuse_w, fusew);

    // 1) proj 1x1 (tf32): fmap = proj_w(256x256) @ x + proj_b
    gemm_tf32<128, 128, 4, 2, false, false, false, true>
        <<<dim3(PIX/128, C_DIM/128, BATCH), 256>>>(
        proj_w, x, fmap, C_DIM, C_DIM, PIX, PIX, 1.f,
        proj_b, nullptr, nullptr,
        0, (size_t)C_DIM*PIX, (size_t)C_DIM*PIX);

    // 2) reduce 1x1
    reduce_kernel<<<dim3(PIX/256, BATCH), 256>>>(fmap, reduce_w, reduce_b, xr);

    // 3) dilated convs
    dilconv_kernel<<<dim3(PIX/256, BATCH, 3), 256>>>(xr, dil_w, dil_b, conv);

    // 4) feats (writes padded zeros too)
    feats_kernel<<<dim3(PIX/256, BATCH), 256>>>(xr, conv, feats);

    // 5) fuse 1x1 (tf32, K padded to 256)
    gemm_tf32<128, 128, 4, 2, false, false, false, true>
        <<<dim3(PIX/128, C_DIM/128, BATCH), 256>>>(
        fusew, feats, tokT, NFPAD, NFPAD, PIX, PIX, 1.f,
        fuse_b, nullptr, nullptr,
        0, (size_t)NFPAD*PIX, (size_t)C_DIM*PIX);

    // 6) transpose -> tok (b,p,c)
    transpose_kernel<<<dim3(PIX/32, C_DIM/32, BATCH), dim3(32, 8)>>>(tokT, tok);

    // 7) scores = (tok @ tok^T)/16 — symmetric: upper-triangle blocks + mirror
    gemm_tf32<128, 128, 4, 2, true, true, false, false>
        <<<dim3(NTRI, 1, BATCH), 256>>>(
        tok, tok, scores, C_DIM, C_DIM, C_DIM, NTOK, 0.0625f,
        nullptr, nullptr, nullptr,
        (size_t)NTOK*C_DIM, (size_t)NTOK*C_DIM, (size_t)NTOK*NTOK);

    // 8) row stats (max, 1/sumexp) — no write-back of the row
    rowstats_kernel<<<dim3(NTOK, BATCH), 256>>>(scores, mx, inv);

    // 9) att = softmax(scores) @ tok — exp fused into A load, inv in epilogue
    gemm_tf32<64, 256, 2, 4, false, false, true, false>
        <<<dim3(1, NTOK/64, BATCH), 256>>>(
        scores, tok, att, NTOK, NTOK, C_DIM, C_DIM, 1.f,
        nullptr, mx, inv,
        (size_t)NTOK*NTOK, (size_t)NTOK*C_DIM, (size_t)NTOK*C_DIM);

    // 10) out = fmap + 0.2 * att^T
    final_kernel<<<dim3(PIX/32, C_DIM/32, BATCH), dim3(32, 8)>>>(fmap, att, out);
}

// round 5
// speedup vs baseline: 1.1678x; 1.1678x over previous
#include <cuda_runtime.h>
#include <cstdint>
#include <cstddef>

// ---------------- problem constants ----------------
#define BATCH 2
#define C_DIM 256
#define HW 96
#define PIX (HW*HW)          // 9216
#define INNER 14
#define NFEAT (INNER*18)     // 252
#define NFPAD 256            // padded feature count for tf32 GEMM
#define NTOK PIX             // 9216

// ---------------- device scratch ----------------
__device__ float g_fmap [BATCH * C_DIM * PIX];
__device__ float g_xr   [BATCH * INNER * PIX];
__device__ float g_conv [3 * BATCH * INNER * PIX];
__device__ float g_feats[BATCH * NFPAD * PIX];
__device__ float g_tokT [BATCH * C_DIM * PIX];
__device__ float g_tok  [BATCH * NTOK * C_DIM];
__device__ float g_scores[(size_t)BATCH * NTOK * NTOK];
__device__ float g_att  [BATCH * NTOK * C_DIM];
__device__ float g_mx   [BATCH * NTOK];
__device__ float g_inv  [BATCH * NTOK];
__device__ float g_fusew[C_DIM * NFPAD];

// ---------------- tf32 helpers ----------------
__device__ __forceinline__ uint32_t f2tf32(float x) {
    uint32_t u;
    asm("cvt.rna.tf32.f32 %0, %1;" : "=r"(u) : "f"(x));
    return u;
}

__device__ __forceinline__ void mma8(float* c, const uint32_t* a, const uint32_t* b) {
    asm volatile(
        "mma.sync.aligned.m16n8k8.row.col.f32.tf32.tf32.f32 "
        "{%0,%1,%2,%3},{%4,%5,%6,%7},{%8,%9},{%0,%1,%2,%3};"
        : "+f"(c[0]), "+f"(c[1]), "+f"(c[2]), "+f"(c[3])
        : "r"(a[0]), "r"(a[1]), "r"(a[2]), "r"(a[3]), "r"(b[0]), "r"(b[1]));
}

// ---------------- tf32 GEMM ----------------
// C = alpha * A~ * op(B) [+ bias]
// A MxK row-major. TB=false: B KxN. TB=true: B NxK.
// EXPA: A-element -> exp(a - mx[row]) on load; epilogue multiplies inv[row].
// BIAS: epilogue adds bias[row].
template<int BM, int BN, int WM, int WN, bool TB, bool EXPA, bool BIAS>
__global__ __launch_bounds__(256, 2)
void gemm_tf32(const float* __restrict__ A, const float* __restrict__ B,
               float* __restrict__ C, int K,
               int lda, int ldb, int ldc, float alpha,
               const float* __restrict__ bias,
               const float* __restrict__ mxp, const float* __restrict__ invp,
               size_t sA, size_t sB, size_t sC)
{
    constexpr int SA = BM + 8;
    constexpr int SB = BN + 8;
    constexpr int NA = BM / 64;
    constexpr int NB = BN / 64;

    __shared__ uint32_t As[2][16 * SA];
    __shared__ uint32_t Bs[2][16 * SB];

    const int bz = blockIdx.z;
    A += (size_t)bz * sA;
    B += (size_t)bz * sB;
    C += (size_t)bz * sC;
    const float* mx  = EXPA ? mxp  + (size_t)bz * NTOK : nullptr;
    const float* inv = EXPA ? invp + (size_t)bz * NTOK : nullptr;

    const int row0 = blockIdx.y * BM;
    const int col0 = blockIdx.x * BN;

    const int tid  = threadIdx.x;
    const int lane = tid & 31;
    const int wid  = tid >> 5;
    const int wm   = wid % WM;
    const int wn   = wid / WM;
    const int g    = lane >> 2;
    const int t4   = lane & 3;
    const int arow = wm * (BM / WM);
    const int bcol = wn * (BN / WN);

    float acc[2][8][4];
    #pragma unroll
    for (int mi = 0; mi < 2; mi++)
        #pragma unroll
        for (int ni = 0; ni < 8; ni++)
            #pragma unroll
            for (int v = 0; v < 4; v++) acc[mi][ni][v] = 0.f;

    float4 ra[NA], rb[NB];
    float mxr[NA > 0 ? NA : 1];
    if (EXPA) {
        #pragma unroll
        for (int u = 0; u < NA; u++) {
            int i = tid + u * 256;
            mxr[u] = mx[row0 + (i >> 2)];
        }
    }

    auto ldgA = [&](int k0) {
        #pragma unroll
        for (int u = 0; u < NA; u++) {
            int i = tid + u * 256;
            int r = i >> 2, k4 = i & 3;
            ra[u] = *(const float4*)(A + (size_t)(row0 + r) * lda + k0 + k4 * 4);
        }
    };
    auto stsA = [&](int buf) {
        #pragma unroll
        for (int u = 0; u < NA; u++) {
            int i = tid + u * 256;
            int r = i >> 2, k4 = i & 3;
            float4 v = ra[u];
            if (EXPA) {
                v.x = __expf(v.x - mxr[u]);
                v.y = __expf(v.y - mxr[u]);
                v.z = __expf(v.z - mxr[u]);
                v.w = __expf(v.w - mxr[u]);
            }
            uint32_t* p = &As[buf][(k4 * 4) * SA + r];
            p[0 * SA] = f2tf32(v.x);
            p[1 * SA] = f2tf32(v.y);
            p[2 * SA] = f2tf32(v.z);
            p[3 * SA] = f2tf32(v.w);
        }
    };
    auto ldgB = [&](int k0) {
        #pragma unroll
        for (int u = 0; u < NB; u++) {
            int i = tid + u * 256;
            if (TB) {
                int n = i >> 2, k4 = i & 3;
                rb[u] = *(const float4*)(B + (size_t)(col0 + n) * ldb + k0 + k4 * 4);
            } else {
                int k = i / (BN / 4), n4 = i % (BN / 4);
                rb[u] = *(const float4*)(B + (size_t)(k0 + k) * ldb + col0 + n4 * 4);
            }
        }
    };
    auto stsB = [&](int buf) {
        #pragma unroll
        for (int u = 0; u < NB; u++) {
            int i = tid + u * 256;
            if (TB) {
                int n = i >> 2, k4 = i & 3;
                uint32_t* p = &Bs[buf][(k4 * 4) * SB + n];
                p[0 * SB] = f2tf32(rb[u].x);
                p[1 * SB] = f2tf32(rb[u].y);
                p[2 * SB] = f2tf32(rb[u].z);
                p[3 * SB] = f2tf32(rb[u].w);
            } else {
                int k = i / (BN / 4), n4 = i % (BN / 4);
                uint4 v;
                v.x = f2tf32(rb[u].x); v.y = f2tf32(rb[u].y);
                v.z = f2tf32(rb[u].z); v.w = f2tf32(rb[u].w);
                *(uint4*)&Bs[buf][k * SB + n4 * 4] = v;
            }
        }
    };

    ldgA(0); ldgB(0);
    stsA(0); stsB(0);
    __syncthreads();

    const int KT = K / 16;
    for (int kt = 0; kt < KT; kt++) {
        int cur = kt & 1, nxt = cur ^ 1;
        if (kt + 1 < KT) { ldgA((kt + 1) * 16); ldgB((kt + 1) * 16); }

        #pragma unroll
        for (int ks = 0; ks < 2; ks++) {
            const int kb = ks * 8;
            uint32_t af[2][4], bf[8][2];
            #pragma unroll
            for (int mi = 0; mi < 2; mi++) {
                int mr = arow + mi * 16 + g;
                af[mi][0] = As[cur][(kb + t4) * SA + mr];
                af[mi][1] = As[cur][(kb + t4) * SA + mr + 8];
                af[mi][2] = As[cur][(kb + t4 + 4) * SA + mr];
                af[mi][3] = As[cur][(kb + t4 + 4) * SA + mr + 8];
            }
            #pragma unroll
            for (int ni = 0; ni < 8; ni++) {
                int nc = bcol + ni * 8 + g;
                bf[ni][0] = Bs[cur][(kb + t4) * SB + nc];
                bf[ni][1] = Bs[cur][(kb + t4 + 4) * SB + nc];
            }
            #pragma unroll
            for (int mi = 0; mi < 2; mi++)
                #pragma unroll
                for (int ni = 0; ni < 8; ni++)
                    mma8(acc[mi][ni], af[mi], bf[ni]);
        }

        if (kt + 1 < KT) { stsA(nxt); stsB(nxt); }
        __syncthreads();
    }

    #pragma unroll
    for (int mi = 0; mi < 2; mi++) {
        int r = row0 + arow + mi * 16 + g;
        float s0 = alpha, s1 = alpha;
        if (EXPA) { s0 *= inv[r]; s1 *= inv[r + 8]; }
        float b0 = 0.f, b1 = 0.f;
        if (BIAS) { b0 = bias[r]; b1 = bias[r + 8]; }
        #pragma unroll
        for (int ni = 0; ni < 8; ni++) {
            int c = col0 + bcol + ni * 8 + t4 * 2;
            float2 v0, v1;
            v0.x = s0 * acc[mi][ni][0] + b0;
            v0.y = s0 * acc[mi][ni][1] + b0;
            v1.x = s1 * acc[mi][ni][2] + b1;
            v1.y = s1 * acc[mi][ni][3] + b1;
            *(float2*)&C[(size_t)r * ldc + c]       = v0;
            *(float2*)&C[(size_t)(r + 8) * ldc + c] = v1;
        }
    }
}

// ---------------- fp32 GEMM (proj 1x1: accuracy-critical) ----------------
__global__ __launch_bounds__(256)
void gemm128(const float* __restrict__ A, const float* __restrict__ Bm,
             float* __restrict__ Cm,
             int M, int Np, int K, int lda, int ldb, int ldc,
             float alpha, const float* __restrict__ bias,
             size_t sA, size_t sB, size_t sC)
{
    __shared__ float As[8][132];
    __shared__ float Bs[8][132];

    int bz = blockIdx.z;
    A  += (size_t)bz * sA;
    Bm += (size_t)bz * sB;
    Cm += (size_t)bz * sC;

    int tid = threadIdx.x;
    int tx = tid % 16;
    int ty = tid / 16;
    int row0 = blockIdx.y * 128;
    int col0 = blockIdx.x * 128;

    float acc[8][8];
    #pragma unroll
    for (int i = 0; i < 8; i++)
        #pragma unroll
        for (int j = 0; j < 8; j++) acc[i][j] = 0.f;

    int a_k = tid % 8;
    int a_m = (tid / 8) * 4;

    for (int k0 = 0; k0 < K; k0 += 8) {
        #pragma unroll
        for (int j = 0; j < 4; j++) {
            int m = a_m + j;
            int kk = k0 + a_k;
            float v = 0.f;
            if (row0 + m < M && kk < K) v = A[(size_t)(row0 + m) * lda + kk];
            As[a_k][m] = v;
        }
        {
            int b_n  = tid % 128;
            int b_kb = (tid / 128) * 4;
            #pragma unroll
            for (int j = 0; j < 4; j++) {
                int kk = k0 + b_kb + j;
                float v = 0.f;
                if (kk < K && col0 + b_n < Np) v = Bm[(size_t)kk * ldb + col0 + b_n];
                Bs[b_kb + j][b_n] = v;
            }
        }
        __syncthreads();

        #pragma unroll
        for (int kk = 0; kk < 8; kk++) {
            float a[8], b[8];
            #pragma unroll
            for (int i = 0; i < 8; i++) a[i] = As[kk][ty * 8 + i];
            #pragma unroll
            for (int j = 0; j < 8; j++) b[j] = Bs[kk][tx * 8 + j];
            #pragma unroll
            for (int i = 0; i < 8; i++)
                #pragma unroll
                for (int j = 0; j < 8; j++)
                    acc[i][j] += a[i] * b[j];
        }
        __syncthreads();
    }

    #pragma unroll
    for (int i = 0; i < 8; i++) {
        int m = row0 + ty * 8 + i;
        if (m >= M) continue;
        float bv = bias ? bias[m] : 0.f;
        #pragma unroll
        for (int j = 0; j < 8; j++) {
            int n = col0 + tx * 8 + j;
            if (n < Np) Cm[(size_t)m * ldc + n] = alpha * acc[i][j] + bv;
        }
    }
}

// ---------------- pad fuse weights 252 -> 256 K ----------------
__global__ __launch_bounds__(256)
void copyw_kernel(const float* __restrict__ w, float* __restrict__ wp)
{
    int r = blockIdx.x;
    int k = threadIdx.x;
    wp[r * NFPAD + k] = (k < NFEAT) ? w[r * NFEAT + k] : 0.f;
}

// ---------------- reduce ----------------
__global__ __launch_bounds__(256)
void reduce_kernel(const float* __restrict__ fmap, const float* __restrict__ w,
                   const float* __restrict__ bias, float* __restrict__ xr)
{
    __shared__ float ws[INNER * C_DIM];
    int tid = threadIdx.x;
    for (int i = tid; i < INNER * C_DIM; i += 256) ws[i] = w[i];
    __syncthreads();

    int b = blockIdx.y;
    int p = blockIdx.x * 256 + tid;
    const float* fin = fmap + (size_t)b * C_DIM * PIX;
    float acc[INNER];
    #pragma unroll
    for (int o = 0; o < INNER; o++) acc[o] = 0.f;
    for (int ci = 0; ci < C_DIM; ci++) {
        float v = fin[(size_t)ci * PIX + p];
        #pragma unroll
        for (int o = 0; o < INNER; o++) acc[o] += ws[o * C_DIM + ci] * v;
    }
    float* xo = xr + (size_t)b * INNER * PIX;
    #pragma unroll
    for (int o = 0; o < INNER; o++) xo[(size_t)o * PIX + p] = acc[o] + bias[o];
}

// ---------------- dilated 3x3 conv ----------------
__global__ __launch_bounds__(256)
void dilconv_kernel(const float* __restrict__ xr, const float* __restrict__ dw,
                    const float* __restrict__ db, float* __restrict__ conv)
{
    __shared__ float ws[INNER * INNER * 9];
    int i = blockIdx.z;
    int d = i + 1;
    int b = blockIdx.y;
    int tid = threadIdx.x;
    for (int k = tid; k < INNER * INNER * 9; k += 256)
        ws[k] = dw[(size_t)i * INNER * INNER * 9 + k];
    __syncthreads();

    int p = blockIdx.x * 256 + tid;
    int h = p / HW, w = p % HW;
    const float* xin = xr + (size_t)b * INNER * PIX;
    float acc[INNER];
    #pragma unroll
    for (int co = 0; co < INNER; co++) acc[co] = 0.f;

    #pragma unroll
    for (int kh = 0; kh < 3; kh++) {
        int hh = h + (kh - 1) * d;
        if (hh < 0 || hh >= HW) continue;
        #pragma unroll
        for (int kw = 0; kw < 3; kw++) {
            int ww = w + (kw - 1) * d;
            if (ww < 0 || ww >= HW) continue;
            int q = hh * HW + ww;
            for (int ci = 0; ci < INNER; ci++) {
                float v = xin[(size_t)ci * PIX + q];
                int widx = ci * 9 + kh * 3 + kw;
                #pragma unroll
                for (int co = 0; co < INNER; co++)
                    acc[co] += ws[co * (INNER * 9) + widx] * v;
            }
        }
    }
    float* cout = conv + ((size_t)(i * BATCH + b) * INNER) * PIX;
    #pragma unroll
    for (int co = 0; co < INNER; co++)
        cout[(size_t)co * PIX + p] = acc[co] + db[i * INNER + co];
}

// ---------------- feats (+ zero padding channels) ----------------
__global__ __launch_bounds__(256)
void feats_kernel(const float* __restrict__ xr, const float* __restrict__ conv,
                  float* __restrict__ feats)
{
    int b = blockIdx.y;
    int p = blockIdx.x * 256 + threadIdx.x;
    int h = p / HW, w = p % HW;
    const float* xin = xr + (size_t)b * INNER * PIX;
    float* fo = feats + (size_t)b * NFPAD * PIX;

    int q[6];
    q[0] = p;
    q[1] = h * HW + (HW - 1 - w);
    q[2] = (HW - 1 - h) * HW + w;
    q[3] = w * HW + (HW - 1 - h);
    q[4] = (HW - 1 - h) * HW + (HW - 1 - w);
    q[5] = (HW - 1 - w) * HW + h;

    for (int c = 0; c < INNER; c++) {
        float cv[3];
        #pragma unroll
        for (int i = 0; i < 3; i++)
            cv[i] = conv[((size_t)(i * BATCH + b) * INNER + c) * PIX + p];
        float tv[6];
        #pragma unroll
        for (int t = 0; t < 6; t++)
            tv[t] = xin[(size_t)c * PIX + q[t]];
        #pragma unroll
        for (int i = 0; i < 3; i++)
            #pragma unroll
            for (int t = 0; t < 6; t++)
                fo[((size_t)((i * 6 + t) * INNER + c)) * PIX + p] = cv[i] * tv[t];
    }
    #pragma unroll
    for (int f = NFEAT; f < NFPAD; f++)
        fo[(size_t)f * PIX + p] = 0.f;
}

// ---------------- transpose ----------------
__global__ __launch_bounds__(256)
void transpose_kernel(const float* __restrict__ src, float* __restrict__ dst)
{
    __shared__ float tile[32][33];
    int b = blockIdx.z;
    int p0 = blockIdx.x * 32, c0 = blockIdx.y * 32;
    const float* s = src + (size_t)b * C_DIM * PIX;
    float* d = dst + (size_t)b * NTOK * C_DIM;
    int tx = threadIdx.x, ty = threadIdx.y;
    #pragma unroll
    for (int j = 0; j < 32; j += 8)
        tile[ty + j][tx] = s[(size_t)(c0 + ty + j) * PIX + p0 + tx];
    __syncthreads();
    #pragma unroll
    for (int j = 0; j < 32; j += 8)
        d[(size_t)(p0 + ty + j) * C_DIM + c0 + tx] = tile[tx][ty + j];
}

// ---------------- row stats: max + 1/sum(exp) ----------------
__global__ __launch_bounds__(256)
void rowstats_kernel(const float* __restrict__ S, float* __restrict__ mx,
                     float* __restrict__ inv)
{
    __shared__ float buf[NTOK];
    __shared__ float red[256];
    int n = blockIdx.x, b = blockIdx.y;
    const float* row = S + ((size_t)b * NTOK + n) * NTOK;
    int tid = threadIdx.x;

    float m = -1e30f;
    for (int i = tid; i < NTOK; i += 256) { float v = row[i]; buf[i] = v; m = fmaxf(m, v); }
    red[tid] = m; __syncthreads();
    for (int s = 128; s > 0; s >>= 1) { if (tid < s) red[tid] = fmaxf(red[tid], red[tid + s]); __syncthreads(); }
    m = red[0];
    __syncthreads();

    float sum = 0.f;
    for (int i = tid; i < NTOK; i += 256) sum += __expf(buf[i] - m);
    red[tid] = sum; __syncthreads();
    for (int s = 128; s > 0; s >>= 1) { if (tid < s) red[tid] += red[tid + s]; __syncthreads(); }

    if (tid == 0) {
        mx[(size_t)b * NTOK + n]  = m;
        inv[(size_t)b * NTOK + n] = 1.f / red[0];
    }
}

// ---------------- final ----------------
__global__ __launch_bounds__(256)
void final_kernel(const float* __restrict__ fmap, const float* __restrict__ att,
                  float* __restrict__ out)
{
    __shared__ float tile[32][33];
    int b = blockIdx.z;
    int p0 = blockIdx.x * 32, c0 = blockIdx.y * 32;
    int tx = threadIdx.x, ty = threadIdx.y;
    const float* a = att + (size_t)b * NTOK * C_DIM;
    #pragma unroll
    for (int j = 0; j < 32; j += 8)
        tile[ty + j][tx] = a[(size_t)(p0 + ty + j) * C_DIM + c0 + tx];
    __syncthreads();
    const float* f = fmap + (size_t)b * C_DIM * PIX;
    float* o = out + (size_t)b * C_DIM * PIX;
    #pragma unroll
    for (int j = 0; j < 32; j += 8) {
        int c = c0 + ty + j, p = p0 + tx;
        o[(size_t)c * PIX + p] = f[(size_t)c * PIX + p] + 0.2f * tile[tx][ty + j];
    }
}

// ---------------- launch ----------------
extern "C" void kernel_launch(void* const* d_in, const int* in_sizes, int n_in,
                              void* d_out, int out_size)
{
    const float* x        = (const float*)d_in[0];
    const float* proj_w   = (const float*)d_in[1];
    const float* proj_b   = (const float*)d_in[2];
    const float* reduce_w = (const float*)d_in[3];
    const float* reduce_b = (const float*)d_in[4];
    const float* dil_w    = (const float*)d_in[5];
    const float* dil_b    = (const float*)d_in[6];
    const float* fuse_w   = (const float*)d_in[7];
    const float* fuse_b   = (const float*)d_in[8];
    float* out = (float*)d_out;

    void *p_fmap, *p_xr, *p_conv, *p_feats, *p_tokT, *p_tok, *p_scores, *p_att,
         *p_mx, *p_inv, *p_fusew;
    cudaGetSymbolAddress(&p_fmap,   g_fmap);
    cudaGetSymbolAddress(&p_xr,     g_xr);
    cudaGetSymbolAddress(&p_conv,   g_conv);
    cudaGetSymbolAddress(&p_feats,  g_feats);
    cudaGetSymbolAddress(&p_tokT,   g_tokT);
    cudaGetSymbolAddress(&p_tok,    g_tok);
    cudaGetSymbolAddress(&p_scores, g_scores);
    cudaGetSymbolAddress(&p_att,    g_att);
    cudaGetSymbolAddress(&p_mx,     g_mx);
    cudaGetSymbolAddress(&p_inv,    g_inv);
    cudaGetSymbolAddress(&p_fusew,  g_fusew);

    float* fmap   = (float*)p_fmap;
    float* xr     = (float*)p_xr;
    float* conv   = (float*)p_conv;
    float* feats  = (float*)p_feats;
    float* tokT   = (float*)p_tokT;
    float* tok    = (float*)p_tok;
    float* scores = (float*)p_scores;
    float* att    = (float*)p_att;
    float* mx     = (float*)p_mx;
    float* inv    = (float*)p_inv;
    float* fusew  = (float*)p_fusew;

    // 0) pad fuse weights
    copyw_kernel<<<C_DIM, 256>>>(fuse_w, fusew);

    // 1) proj 1x1 — fp32 (accuracy-critical: feeds residual directly)
    gemm128<<<dim3(PIX/128, C_DIM/128, BATCH), 256>>>(
        proj_w, x, fmap, C_DIM, PIX, C_DIM, C_DIM, PIX, PIX,
        1.f, proj_b, 0, (size_t)C_DIM*PIX, (size_t)C_DIM*PIX);

    // 2) reduce 1x1
    reduce_kernel<<<dim3(PIX/256, BATCH), 256>>>(fmap, reduce_w, reduce_b, xr);

    // 3) dilated convs
    dilconv_kernel<<<dim3(PIX/256, BATCH, 3), 256>>>(xr, dil_w, dil_b, conv);

    // 4) feats (writes padded zeros too)
    feats_kernel<<<dim3(PIX/256, BATCH), 256>>>(xr, conv, feats);

    // 5) fuse 1x1 (tf32, K padded to 256)
    gemm_tf32<128, 128, 4, 2, false, false, true>
        <<<dim3(PIX/128, C_DIM/128, BATCH), 256>>>(
        fusew, feats, tokT, NFPAD, NFPAD, PIX, PIX, 1.f,
        fuse_b, nullptr, nullptr,
        0, (size_t)NFPAD*PIX, (size_t)C_DIM*PIX);

    // 6) transpose -> tok (b,p,c)
    transpose_kernel<<<dim3(PIX/32, C_DIM/32, BATCH), dim3(32, 8)>>>(tokT, tok);

    // 7) scores = (tok @ tok^T)/16 — full grid, coalesced stores
    gemm_tf32<128, 128, 4, 2, true, false, false>
        <<<dim3(NTOK/128, NTOK/128, BATCH), 256>>>(
        tok, tok, scores, C_DIM, C_DIM, C_DIM, NTOK, 0.0625f,
        nullptr, nullptr, nullptr,
        (size_t)NTOK*C_DIM, (size_t)NTOK*C_DIM, (size_t)NTOK*NTOK);

    // 8) row stats (max, 1/sumexp) — no write-back of the row
    rowstats_kernel<<<dim3(NTOK, BATCH), 256>>>(scores, mx, inv);

    // 9) att = softmax(scores) @ tok — exp fused into A load, inv in epilogue
    gemm_tf32<64, 256, 2, 4, false, true, false>
        <<<dim3(1, NTOK/64, BATCH), 256>>>(
        scores, tok, att, NTOK, NTOK, C_DIM, C_DIM, 1.f,
        nullptr, mx, inv,
        (size_t)NTOK*NTOK, (size_t)NTOK*C_DIM, (size_t)NTOK*C_DIM);

    // 10) out = fmap + 0.2 * att^T
    final_kernel<<<dim3(PIX/32, C_DIM/32, BATCH), dim3(32, 8)>>>(fmap, att, out);
}

// round 6
// speedup vs baseline: 1.7593x; 1.5064x over previous
#include <cuda_runtime.h>
#include <cuda_fp16.h>
#include <cstdint>
#include <cstddef>

// ---------------- problem constants ----------------
#define BATCH 2
#define C_DIM 256
#define HW 96
#define PIX (HW*HW)          // 9216
#define INNER 14
#define NFEAT (INNER*18)     // 252
#define NFPAD 256
#define NTOK PIX             // 9216
#define NBLK (NTOK/128)      // 72 col-blocks of scores

// ---------------- device scratch ----------------
__device__ float g_fmap [BATCH * C_DIM * PIX];
__device__ float g_xr   [BATCH * INNER * PIX];
__device__ float g_conv [3 * BATCH * INNER * PIX];
__device__ float g_feats[BATCH * NFPAD * PIX];
__device__ float g_tokT [BATCH * C_DIM * PIX];
__device__ float g_tok  [BATCH * NTOK * C_DIM];
__device__ float g_scores[(size_t)BATCH * NTOK * NTOK];
__device__ float g_att  [BATCH * NTOK * C_DIM];
__device__ float g_mx   [BATCH * NTOK];
__device__ float g_inv  [BATCH * NTOK];
__device__ float g_fusew[C_DIM * NFPAD];
__device__ float g_pm   [(size_t)BATCH * NBLK * NTOK];   // per-colblock row max
__device__ float g_ps   [(size_t)BATCH * NBLK * NTOK];   // per-colblock row sumexp

// ---------------- fp16 helpers ----------------
__device__ __forceinline__ uint32_t pk(float lo, float hi) {
    uint32_t u;
    asm("cvt.rn.f16x2.f32 %0, %1, %2;" : "=r"(u) : "f"(hi), "f"(lo));
    return u;
}

__device__ __forceinline__ void mma16(float* c, const uint32_t* a, const uint32_t* b) {
    asm volatile(
        "mma.sync.aligned.m16n8k16.row.col.f32.f16.f16.f32 "
        "{%0,%1,%2,%3},{%4,%5,%6,%7},{%8,%9},{%0,%1,%2,%3};"
        : "+f"(c[0]), "+f"(c[1]), "+f"(c[2]), "+f"(c[3])
        : "r"(a[0]), "r"(a[1]), "r"(a[2]), "r"(a[3]), "r"(b[0]), "r"(b[1]));
}

// ---------------- fp16 GEMM: C = alpha * A~ * op(B) [+ bias] ----------------
// A MxK row-major fp32 (converted to fp16 in smem). TB=false: B KxN. TB=true: B NxK.
// EXPA : A-element -> exp(a - mx[row]) on load; epilogue multiplies inv[row].
// BIAS : epilogue adds bias[row].
// STATS: epilogue emits per-(row, colblock) max and sum(exp(s - max)) partials.
// BK = 16 (one m16n8k16 per k-tile). Smem holds half2 pairs along k.
template<int BM, int BN, int WM, int WN, bool TB, bool EXPA, bool BIAS, bool STATS>
__global__ __launch_bounds__(256, 2)
void gemm_f16(const float* __restrict__ A, const float* __restrict__ B,
              float* __restrict__ C, int K, int lda, int ldb, int ldc,
              float alpha, const float* __restrict__ bias,
              const float* __restrict__ mxp, const float* __restrict__ invp,
              float* __restrict__ pm, float* __restrict__ ps,
              size_t sA, size_t sB, size_t sC)
{
    constexpr int SA = BM + 8;   // uint32 (half2) stride; conflict-free frag LDS
    constexpr int SB = BN + 8;
    constexpr int NA = BM / 64;  // A float4 slots per thread
    constexpr int NB = BN / 64;  // B float4 slots per thread (TB=true)
    constexpr int SL = BN / 128; // B pair-slots per thread (TB=false)

    __shared__ uint32_t As[2][8 * SA];
    __shared__ uint32_t Bs[2][8 * SB];
    __shared__ float redm[WN][BM];
    __shared__ float reds[WN][BM];

    const int bz = blockIdx.z;
    A += (size_t)bz * sA;
    B += (size_t)bz * sB;
    C += (size_t)bz * sC;
    const float* mx  = EXPA ? mxp  + (size_t)bz * NTOK : nullptr;
    const float* inv = EXPA ? invp + (size_t)bz * NTOK : nullptr;

    const int row0 = blockIdx.y * BM;
    const int col0 = blockIdx.x * BN;

    const int tid  = threadIdx.x;
    const int lane = tid & 31;
    const int wid  = tid >> 5;
    const int wm   = wid % WM;
    const int wn   = wid / WM;
    const int g    = lane >> 2;
    const int t4   = lane & 3;
    const int arow = wm * (BM / WM);
    const int bcol = wn * (BN / WN);

    float acc[2][8][4];
    #pragma unroll
    for (int mi = 0; mi < 2; mi++)
        #pragma unroll
        for (int ni = 0; ni < 8; ni++)
            #pragma unroll
            for (int v = 0; v < 4; v++) acc[mi][ni][v] = 0.f;

    float4 ra[NA];
    float4 rbt[NB];
    float4 rb0[SL], rb1[SL];
    float mxr[NA];
    if (EXPA) {
        #pragma unroll
        for (int u = 0; u < NA; u++)
            mxr[u] = mx[row0 + ((tid + u * 256) >> 2)];
    }

    auto ldgA = [&](int k0) {
        #pragma unroll
        for (int u = 0; u < NA; u++) {
            int i = tid + u * 256;
            int r = i >> 2, k4 = i & 3;
            ra[u] = *(const float4*)(A + (size_t)(row0 + r) * lda + k0 + k4 * 4);
        }
    };
    auto stsA = [&](int buf) {
        #pragma unroll
        for (int u = 0; u < NA; u++) {
            int i = tid + u * 256;
            int r = i >> 2, k4 = i & 3;
            float4 v = ra[u];
            if (EXPA) {
                v.x = __expf(v.x - mxr[u]);
                v.y = __expf(v.y - mxr[u]);
                v.z = __expf(v.z - mxr[u]);
                v.w = __expf(v.w - mxr[u]);
            }
            As[buf][(k4 * 2) * SA + r]     = pk(v.x, v.y);
            As[buf][(k4 * 2 + 1) * SA + r] = pk(v.z, v.w);
        }
    };
    auto ldgB = [&](int k0) {
        if constexpr (TB) {
            #pragma unroll
            for (int u = 0; u < NB; u++) {
                int i = tid + u * 256;
                int n = i >> 2, k4 = i & 3;
                rbt[u] = *(const float4*)(B + (size_t)(col0 + n) * ldb + k0 + k4 * 4);
            }
        } else {
            #pragma unroll
            for (int u = 0; u < SL; u++) {
                int i = tid + u * 256;
                int kp = i / (BN / 4), n4 = i % (BN / 4);
                const float* p = B + (size_t)(k0 + 2 * kp) * ldb + col0 + n4 * 4;
                rb0[u] = *(const float4*)p;
                rb1[u] = *(const float4*)(p + ldb);
            }
        }
    };
    auto stsB = [&](int buf) {
        if constexpr (TB) {
            #pragma unroll
            for (int u = 0; u < NB; u++) {
                int i = tid + u * 256;
                int n = i >> 2, k4 = i & 3;
                Bs[buf][(k4 * 2) * SB + n]     = pk(rbt[u].x, rbt[u].y);
                Bs[buf][(k4 * 2 + 1) * SB + n] = pk(rbt[u].z, rbt[u].w);
            }
        } else {
            #pragma unroll
            for (int u = 0; u < SL; u++) {
                int i = tid + u * 256;
                int kp = i / (BN / 4), n4 = i % (BN / 4);
                uint4 v;
                v.x = pk(rb0[u].x, rb1[u].x);
                v.y = pk(rb0[u].y, rb1[u].y);
                v.z = pk(rb0[u].z, rb1[u].z);
                v.w = pk(rb0[u].w, rb1[u].w);
                *(uint4*)&Bs[buf][kp * SB + n4 * 4] = v;
            }
        }
    };

    ldgA(0); ldgB(0);
    stsA(0); stsB(0);
    __syncthreads();

    const int KT = K / 16;
    for (int kt = 0; kt < KT; kt++) {
        int cur = kt & 1, nxt = cur ^ 1;
        if (kt + 1 < KT) { ldgA((kt + 1) * 16); ldgB((kt + 1) * 16); }

        uint32_t af[2][4], bf[8][2];
        #pragma unroll
        for (int mi = 0; mi < 2; mi++) {
            int mr = arow + mi * 16 + g;
            af[mi][0] = As[cur][t4 * SA + mr];
            af[mi][1] = As[cur][t4 * SA + mr + 8];
            af[mi][2] = As[cur][(t4 + 4) * SA + mr];
            af[mi][3] = As[cur][(t4 + 4) * SA + mr + 8];
        }
        #pragma unroll
        for (int ni = 0; ni < 8; ni++) {
            int nc = bcol + ni * 8 + g;
            bf[ni][0] = Bs[cur][t4 * SB + nc];
            bf[ni][1] = Bs[cur][(t4 + 4) * SB + nc];
        }
        #pragma unroll
        for (int mi = 0; mi < 2; mi++)
            #pragma unroll
            for (int ni = 0; ni < 8; ni++)
                mma16(acc[mi][ni], af[mi], bf[ni]);

        if (kt + 1 < KT) { stsA(nxt); stsB(nxt); }
        __syncthreads();
    }

    // ---- store C ----
    #pragma unroll
    for (int mi = 0; mi < 2; mi++) {
        int r = row0 + arow + mi * 16 + g;
        float s0 = alpha, s1 = alpha;
        if (EXPA) { s0 *= inv[r]; s1 *= inv[r + 8]; }
        float b0 = 0.f, b1 = 0.f;
        if (BIAS) { b0 = bias[r]; b1 = bias[r + 8]; }
        #pragma unroll
        for (int ni = 0; ni < 8; ni++) {
            int c = col0 + bcol + ni * 8 + t4 * 2;
            float2 v0, v1;
            v0.x = s0 * acc[mi][ni][0] + b0;
            v0.y = s0 * acc[mi][ni][1] + b0;
            v1.x = s1 * acc[mi][ni][2] + b1;
            v1.y = s1 * acc[mi][ni][3] + b1;
            *(float2*)&C[(size_t)r * ldc + c]       = v0;
            *(float2*)&C[(size_t)(r + 8) * ldc + c] = v1;
        }
    }

    // ---- fused softmax partial stats (scores GEMM only) ----
    if (STATS) {
        float mrow[2][2];
        #pragma unroll
        for (int mi = 0; mi < 2; mi++)
            #pragma unroll
            for (int hf = 0; hf < 2; hf++) {
                float m = -1e30f;
                #pragma unroll
                for (int ni = 0; ni < 8; ni++)
                    m = fmaxf(m, fmaxf(acc[mi][ni][hf * 2], acc[mi][ni][hf * 2 + 1]));
                m *= alpha;   // alpha > 0
                m = fmaxf(m, __shfl_xor_sync(0xffffffffu, m, 1));
                m = fmaxf(m, __shfl_xor_sync(0xffffffffu, m, 2));
                int rib = arow + mi * 16 + hf * 8 + g;
                if (t4 == 0) redm[wn][rib] = m;
            }
        __syncthreads();
        #pragma unroll
        for (int mi = 0; mi < 2; mi++)
            #pragma unroll
            for (int hf = 0; hf < 2; hf++) {
                int rib = arow + mi * 16 + hf * 8 + g;
                mrow[mi][hf] = fmaxf(redm[0][rib], redm[1][rib]);
            }
        #pragma unroll
        for (int mi = 0; mi < 2; mi++)
            #pragma unroll
            for (int hf = 0; hf < 2; hf++) {
                float m = mrow[mi][hf];
                float s = 0.f;
                #pragma unroll
                for (int ni = 0; ni < 8; ni++) {
                    s += __expf(alpha * acc[mi][ni][hf * 2] - m);
                    s += __expf(alpha * acc[mi][ni][hf * 2 + 1] - m);
                }
                s += __shfl_xor_sync(0xffffffffu, s, 1);
                s += __shfl_xor_sync(0xffffffffu, s, 2);
                int rib = arow + mi * 16 + hf * 8 + g;
                if (t4 == 0) reds[wn][rib] = s;
            }
        __syncthreads();
        if (wn == 0 && t4 == 0) {
            #pragma unroll
            for (int mi = 0; mi < 2; mi++)
                #pragma unroll
                for (int hf = 0; hf < 2; hf++) {
                    int rib = arow + mi * 16 + hf * 8 + g;
                    size_t idx = ((size_t)bz * NBLK + blockIdx.x) * NTOK + row0 + rib;
                    pm[idx] = mrow[mi][hf];
                    ps[idx] = reds[0][rib] + reds[1][rib];
                }
        }
    }
}

// ---------------- combine partial stats -> mx, inv ----------------
__global__ __launch_bounds__(256)
void combine_kernel(const float* __restrict__ pm, const float* __restrict__ ps,
                    float* __restrict__ mx, float* __restrict__ inv)
{
    int r = blockIdx.x * 256 + threadIdx.x;
    int b = blockIdx.y;
    float m = -1e30f;
    for (int cb = 0; cb < NBLK; cb++)
        m = fmaxf(m, pm[((size_t)b * NBLK + cb) * NTOK + r]);
    float s = 0.f;
    for (int cb = 0; cb < NBLK; cb++) {
        size_t idx = ((size_t)b * NBLK + cb) * NTOK + r;
        s += ps[idx] * __expf(pm[idx] - m);
    }
    mx[(size_t)b * NTOK + r]  = m;
    inv[(size_t)b * NTOK + r] = 1.f / s;
}

// ---------------- fp32 GEMM (proj 1x1: accuracy-critical) ----------------
__global__ __launch_bounds__(256)
void gemm128(const float* __restrict__ A, const float* __restrict__ Bm,
             float* __restrict__ Cm,
             int M, int Np, int K, int lda, int ldb, int ldc,
             float alpha, const float* __restrict__ bias,
             size_t sA, size_t sB, size_t sC)
{
    __shared__ float As[8][132];
    __shared__ float Bs[8][132];

    int bz = blockIdx.z;
    A  += (size_t)bz * sA;
    Bm += (size_t)bz * sB;
    Cm += (size_t)bz * sC;

    int tid = threadIdx.x;
    int tx = tid % 16;
    int ty = tid / 16;
    int row0 = blockIdx.y * 128;
    int col0 = blockIdx.x * 128;

    float acc[8][8];
    #pragma unroll
    for (int i = 0; i < 8; i++)
        #pragma unroll
        for (int j = 0; j < 8; j++) acc[i][j] = 0.f;

    int a_k = tid % 8;
    int a_m = (tid / 8) * 4;

    for (int k0 = 0; k0 < K; k0 += 8) {
        #pragma unroll
        for (int j = 0; j < 4; j++) {
            int m = a_m + j;
            int kk = k0 + a_k;
            float v = 0.f;
            if (row0 + m < M && kk < K) v = A[(size_t)(row0 + m) * lda + kk];
            As[a_k][m] = v;
        }
        {
            int b_n  = tid % 128;
            int b_kb = (tid / 128) * 4;
            #pragma unroll
            for (int j = 0; j < 4; j++) {
                int kk = k0 + b_kb + j;
                float v = 0.f;
                if (kk < K && col0 + b_n < Np) v = Bm[(size_t)kk * ldb + col0 + b_n];
                Bs[b_kb + j][b_n] = v;
            }
        }
        __syncthreads();

        #pragma unroll
        for (int kk = 0; kk < 8; kk++) {
            float a[8], b[8];
            #pragma unroll
            for (int i = 0; i < 8; i++) a[i] = As[kk][ty * 8 + i];
            #pragma unroll
            for (int j = 0; j < 8; j++) b[j] = Bs[kk][tx * 8 + j];
            #pragma unroll
            for (int i = 0; i < 8; i++)
                #pragma unroll
                for (int j = 0; j < 8; j++)
                    acc[i][j] += a[i] * b[j];
        }
        __syncthreads();
    }

    #pragma unroll
    for (int i = 0; i < 8; i++) {
        int m = row0 + ty * 8 + i;
        if (m >= M) continue;
        float bv = bias ? bias[m] : 0.f;
        #pragma unroll
        for (int j = 0; j < 8; j++) {
            int n = col0 + tx * 8 + j;
            if (n < Np) Cm[(size_t)m * ldc + n] = alpha * acc[i][j] + bv;
        }
    }
}

// ---------------- pad fuse weights 252 -> 256 K ----------------
__global__ __launch_bounds__(256)
void copyw_kernel(const float* __restrict__ w, float* __restrict__ wp)
{
    int r = blockIdx.x;
    int k = threadIdx.x;
    wp[r * NFPAD + k] = (k < NFEAT) ? w[r * NFEAT + k] : 0.f;
}

// ---------------- reduce ----------------
__global__ __launch_bounds__(256)
void reduce_kernel(const float* __restrict__ fmap, const float* __restrict__ w,
                   const float* __restrict__ bias, float* __restrict__ xr)
{
    __shared__ float ws[INNER * C_DIM];
    int tid = threadIdx.x;
    for (int i = tid; i < INNER * C_DIM; i += 256) ws[i] = w[i];
    __syncthreads();

    int b = blockIdx.y;
    int p = blockIdx.x * 256 + tid;
    const float* fin = fmap + (size_t)b * C_DIM * PIX;
    float acc[INNER];
    #pragma unroll
    for (int o = 0; o < INNER; o++) acc[o] = 0.f;
    for (int ci = 0; ci < C_DIM; ci++) {
        float v = fin[(size_t)ci * PIX + p];
        #pragma unroll
        for (int o = 0; o < INNER; o++) acc[o] += ws[o * C_DIM + ci] * v;
    }
    float* xo = xr + (size_t)b * INNER * PIX;
    #pragma unroll
    for (int o = 0; o < INNER; o++) xo[(size_t)o * PIX + p] = acc[o] + bias[o];
}

// ---------------- dilated 3x3 conv ----------------
__global__ __launch_bounds__(256)
void dilconv_kernel(const float* __restrict__ xr, const float* __restrict__ dw,
                    const float* __restrict__ db, float* __restrict__ conv)
{
    __shared__ float ws[INNER * INNER * 9];
    int i = blockIdx.z;
    int d = i + 1;
    int b = blockIdx.y;
    int tid = threadIdx.x;
    for (int k = tid; k < INNER * INNER * 9; k += 256)
        ws[k] = dw[(size_t)i * INNER * INNER * 9 + k];
    __syncthreads();

    int p = blockIdx.x * 256 + tid;
    int h = p / HW, w = p % HW;
    const float* xin = xr + (size_t)b * INNER * PIX;
    float acc[INNER];
    #pragma unroll
    for (int co = 0; co < INNER; co++) acc[co] = 0.f;

    #pragma unroll
    for (int kh = 0; kh < 3; kh++) {
        int hh = h + (kh - 1) * d;
        if (hh < 0 || hh >= HW) continue;
        #pragma unroll
        for (int kw = 0; kw < 3; kw++) {
            int ww = w + (kw - 1) * d;
            if (ww < 0 || ww >= HW) continue;
            int q = hh * HW + ww;
            for (int ci = 0; ci < INNER; ci++) {
                float v = xin[(size_t)ci * PIX + q];
                int widx = ci * 9 + kh * 3 + kw;
                #pragma unroll
                for (int co = 0; co < INNER; co++)
                    acc[co] += ws[co * (INNER * 9) + widx] * v;
            }
        }
    }
    float* cout = conv + ((size_t)(i * BATCH + b) * INNER) * PIX;
    #pragma unroll
    for (int co = 0; co < INNER; co++)
        cout[(size_t)co * PIX + p] = acc[co] + db[i * INNER + co];
}

// ---------------- feats (+ zero padding channels) ----------------
__global__ __launch_bounds__(256)
void feats_kernel(const float* __restrict__ xr, const float* __restrict__ conv,
                  float* __restrict__ feats)
{
    int b = blockIdx.y;
    int p = blockIdx.x * 256 + threadIdx.x;
    int h = p / HW, w = p % HW;
    const float* xin = xr + (size_t)b * INNER * PIX;
    float* fo = feats + (size_t)b * NFPAD * PIX;

    int q[6];
    q[0] = p;
    q[1] = h * HW + (HW - 1 - w);
    q[2] = (HW - 1 - h) * HW + w;
    q[3] = w * HW + (HW - 1 - h);
    q[4] = (HW - 1 - h) * HW + (HW - 1 - w);
    q[5] = (HW - 1 - w) * HW + h;

    for (int c = 0; c < INNER; c++) {
        float cv[3];
        #pragma unroll
        for (int i = 0; i < 3; i++)
            cv[i] = conv[((size_t)(i * BATCH + b) * INNER + c) * PIX + p];
        float tv[6];
        #pragma unroll
        for (int t = 0; t < 6; t++)
            tv[t] = xin[(size_t)c * PIX + q[t]];
        #pragma unroll
        for (int i = 0; i < 3; i++)
            #pragma unroll
            for (int t = 0; t < 6; t++)
                fo[((size_t)((i * 6 + t) * INNER + c)) * PIX + p] = cv[i] * tv[t];
    }
    #pragma unroll
    for (int f = NFEAT; f < NFPAD; f++)
        fo[(size_t)f * PIX + p] = 0.f;
}

// ---------------- transpose ----------------
__global__ __launch_bounds__(256)
void transpose_kernel(const float* __restrict__ src, float* __restrict__ dst)
{
    __shared__ float tile[32][33];
    int b = blockIdx.z;
    int p0 = blockIdx.x * 32, c0 = blockIdx.y * 32;
    const float* s = src + (size_t)b * C_DIM * PIX;
    float* d = dst + (size_t)b * NTOK * C_DIM;
    int tx = threadIdx.x, ty = threadIdx.y;
    #pragma unroll
    for (int j = 0; j < 32; j += 8)
        tile[ty + j][tx] = s[(size_t)(c0 + ty + j) * PIX + p0 + tx];
    __syncthreads();
    #pragma unroll
    for (int j = 0; j < 32; j += 8)
        d[(size_t)(p0 + ty + j) * C_DIM + c0 + tx] = tile[tx][ty + j];
}

// ---------------- final ----------------
__global__ __launch_bounds__(256)
void final_kernel(const float* __restrict__ fmap, const float* __restrict__ att,
                  float* __restrict__ out)
{
    __shared__ float tile[32][33];
    int b = blockIdx.z;
    int p0 = blockIdx.x * 32, c0 = blockIdx.y * 32;
    int tx = threadIdx.x, ty = threadIdx.y;
    const float* a = att + (size_t)b * NTOK * C_DIM;
    #pragma unroll
    for (int j = 0; j < 32; j += 8)
        tile[ty + j][tx] = a[(size_t)(p0 + ty + j) * C_DIM + c0 + tx];
    __syncthreads();
    const float* f = fmap + (size_t)b * C_DIM * PIX;
    float* o = out + (size_t)b * C_DIM * PIX;
    #pragma unroll
    for (int j = 0; j < 32; j += 8) {
        int c = c0 + ty + j, p = p0 + tx;
        o[(size_t)c * PIX + p] = f[(size_t)c * PIX + p] + 0.2f * tile[tx][ty + j];
    }
}

// ---------------- launch ----------------
extern "C" void kernel_launch(void* const* d_in, const int* in_sizes, int n_in,
                              void* d_out, int out_size)
{
    const float* x        = (const float*)d_in[0];
    const float* proj_w   = (const float*)d_in[1];
    const float* proj_b   = (const float*)d_in[2];
    const float* reduce_w = (const float*)d_in[3];
    const float* reduce_b = (const float*)d_in[4];
    const float* dil_w    = (const float*)d_in[5];
    const float* dil_b    = (const float*)d_in[6];
    const float* fuse_w   = (const float*)d_in[7];
    const float* fuse_b   = (const float*)d_in[8];
    float* out = (float*)d_out;

    void *p_fmap, *p_xr, *p_conv, *p_feats, *p_tokT, *p_tok, *p_scores, *p_att,
         *p_mx, *p_inv, *p_fusew, *p_pm, *p_ps;
    cudaGetSymbolAddress(&p_fmap,   g_fmap);
    cudaGetSymbolAddress(&p_xr,     g_xr);
    cudaGetSymbolAddress(&p_conv,   g_conv);
    cudaGetSymbolAddress(&p_feats,  g_feats);
    cudaGetSymbolAddress(&p_tokT,   g_tokT);
    cudaGetSymbolAddress(&p_tok,    g_tok);
    cudaGetSymbolAddress(&p_scores, g_scores);
    cudaGetSymbolAddress(&p_att,    g_att);
    cudaGetSymbolAddress(&p_mx,     g_mx);
    cudaGetSymbolAddress(&p_inv,    g_inv);
    cudaGetSymbolAddress(&p_fusew,  g_fusew);
    cudaGetSymbolAddress(&p_pm,     g_pm);
    cudaGetSymbolAddress(&p_ps,     g_ps);

    float* fmap   = (float*)p_fmap;
    float* xr     = (float*)p_xr;
    float* conv   = (float*)p_conv;
    float* feats  = (float*)p_feats;
    float* tokT   = (float*)p_tokT;
    float* tok    = (float*)p_tok;
    float* scores = (float*)p_scores;
    float* att    = (float*)p_att;
    float* mx     = (float*)p_mx;
    float* inv    = (float*)p_inv;
    float* fusew  = (float*)p_fusew;
    float* pm     = (float*)p_pm;
    float* ps     = (float*)p_ps;

    // 0) pad fuse weights
    copyw_kernel<<<C_DIM, 256>>>(fuse_w, fusew);

    // 1) proj 1x1 — fp32 (feeds residual directly)
    gemm128<<<dim3(PIX/128, C_DIM/128, BATCH), 256>>>(
        proj_w, x, fmap, C_DIM, PIX, C_DIM, C_DIM, PIX, PIX,
        1.f, proj_b, 0, (size_t)C_DIM*PIX, (size_t)C_DIM*PIX);

    // 2) reduce 1x1
    reduce_kernel<<<dim3(PIX/256, BATCH), 256>>>(fmap, reduce_w, reduce_b, xr);

    // 3) dilated convs
    dilconv_kernel<<<dim3(PIX/256, BATCH, 3), 256>>>(xr, dil_w, dil_b, conv);

    // 4) feats
    feats_kernel<<<dim3(PIX/256, BATCH), 256>>>(xr, conv, feats);

    // 5) fuse 1x1 — fp16 tensor cores
    gemm_f16<128, 128, 4, 2, false, false, true, false>
        <<<dim3(PIX/128, C_DIM/128, BATCH), 256>>>(
        fusew, feats, tokT, NFPAD, NFPAD, PIX, PIX, 1.f,
        fuse_b, nullptr, nullptr, nullptr, nullptr,
        0, (size_t)NFPAD*PIX, (size_t)C_DIM*PIX);

    // 6) transpose -> tok (b,p,c)
    transpose_kernel<<<dim3(PIX/32, C_DIM/32, BATCH), dim3(32, 8)>>>(tokT, tok);

    // 7) scores = (tok @ tok^T)/16 — fp16, with fused softmax partial stats
    gemm_f16<128, 128, 4, 2, true, false, false, true>
        <<<dim3(NBLK, NBLK, BATCH), 256>>>(
        tok, tok, scores, C_DIM, C_DIM, C_DIM, NTOK, 0.0625f,
        nullptr, nullptr, nullptr, pm, ps,
        (size_t)NTOK*C_DIM, (size_t)NTOK*C_DIM, (size_t)NTOK*NTOK);

    // 8) combine partials -> row max + 1/sumexp  (replaces 680MB rowstats read)
    combine_kernel<<<dim3(NTOK/256, BATCH), 256>>>(pm, ps, mx, inv);

    // 9) att = softmax(scores) @ tok — fp16, exp fused into A load
    gemm_f16<64, 256, 2, 4, false, true, false, false>
        <<<dim3(1, NTOK/64, BATCH), 256>>>(
        scores, tok, att, NTOK, NTOK, C_DIM, C_DIM, 1.f,
        nullptr, mx, inv, nullptr, nullptr,
        (size_t)NTOK*NTOK, (size_t)NTOK*C_DIM, (size_t)NTOK*C_DIM);

    // 10) out = fmap + 0.2 * att^T
    final_kernel<<<dim3(PIX/32, C_DIM/32, BATCH), dim3(32, 8)>>>(fmap, att, out);
}

// round 7
// speedup vs baseline: 1.7692x; 1.0056x over previous
#include <cuda_runtime.h>
#include <cuda_fp16.h>
#include <cstdint>
#include <cstddef>

// ---------------- problem constants ----------------
#define BATCH 2
#define C_DIM 256
#define HW 96
#define PIX (HW*HW)          // 9216
#define INNER 14
#define NFEAT (INNER*18)     // 252
#define NFPAD 256
#define NTOK PIX             // 9216
#define NBLK (NTOK/128)      // 72 col-blocks of scores

// ---------------- device scratch ----------------
__device__ float g_fmap [BATCH * C_DIM * PIX];
__device__ float g_xr   [BATCH * INNER * PIX];
__device__ float g_conv [3 * BATCH * INNER * PIX];
__device__ float g_feats[BATCH * NFPAD * PIX];
__device__ float g_tokT [BATCH * C_DIM * PIX];
__device__ float g_tok  [BATCH * NTOK * C_DIM];
__device__ float g_scores[(size_t)BATCH * NTOK * NTOK];
__device__ float g_att  [BATCH * NTOK * C_DIM];
__device__ float g_mx   [BATCH * NTOK];
__device__ float g_inv  [BATCH * NTOK];
__device__ float g_fusew[C_DIM * NFPAD];
__device__ float g_pm   [(size_t)BATCH * NBLK * NTOK];   // per-colblock row max
__device__ float g_ps   [(size_t)BATCH * NBLK * NTOK];   // per-colblock row sumexp

// ---------------- fp16 helpers ----------------
__device__ __forceinline__ uint32_t pk(float lo, float hi) {
    uint32_t u;
    asm("cvt.rn.f16x2.f32 %0, %1, %2;" : "=r"(u) : "f"(hi), "f"(lo));
    return u;
}

__device__ __forceinline__ void mma16(float* c, const uint32_t* a, const uint32_t* b) {
    asm volatile(
        "mma.sync.aligned.m16n8k16.row.col.f32.f16.f16.f32 "
        "{%0,%1,%2,%3},{%4,%5,%6,%7},{%8,%9},{%0,%1,%2,%3};"
        : "+f"(c[0]), "+f"(c[1]), "+f"(c[2]), "+f"(c[3])
        : "r"(a[0]), "r"(a[1]), "r"(a[2]), "r"(a[3]), "r"(b[0]), "r"(b[1]));
}

// ---------------- fp16 GEMM: C = alpha * A~ * op(B) [+ bias] ----------------
// A MxK row-major fp32 (converted to fp16 in smem). TB=false: B KxN. TB=true: B NxK.
// EXPA : A-element -> exp(a - mx[row]) on load; epilogue multiplies inv[row].
// BIAS : epilogue adds bias[row].
// STATS: epilogue emits per-(row, colblock) max and sum(exp(s - max)) partials.
// BK = 16 (one m16n8k16 per k-tile). Smem holds half2 pairs along k.
template<int BM, int BN, int WM, int WN, bool TB, bool EXPA, bool BIAS, bool STATS>
__global__ __launch_bounds__(256, 2)
void gemm_f16(const float* __restrict__ A, const float* __restrict__ B,
              float* __restrict__ C, int K, int lda, int ldb, int ldc,
              float alpha, const float* __restrict__ bias,
              const float* __restrict__ mxp, const float* __restrict__ invp,
              float* __restrict__ pm, float* __restrict__ ps,
              size_t sA, size_t sB, size_t sC)
{
    constexpr int SA = BM + 8;   // uint32 (half2) stride; conflict-free frag LDS
    constexpr int SB = BN + 8;
    constexpr int NA = BM / 64;  // A float4 slots per thread
    constexpr int NB = BN / 64;  // B float4 slots per thread (TB=true)
    constexpr int SL = BN / 128; // B pair-slots per thread (TB=false)

    __shared__ uint32_t As[2][8 * SA];
    __shared__ uint32_t Bs[2][8 * SB];
    __shared__ float redm[WN][BM];
    __shared__ float reds[WN][BM];

    const int bz = blockIdx.z;
    A += (size_t)bz * sA;
    B += (size_t)bz * sB;
    C += (size_t)bz * sC;
    const float* mx  = EXPA ? mxp  + (size_t)bz * NTOK : nullptr;
    const float* inv = EXPA ? invp + (size_t)bz * NTOK : nullptr;

    const int row0 = blockIdx.y * BM;
    const int col0 = blockIdx.x * BN;

    const int tid  = threadIdx.x;
    const int lane = tid & 31;
    const int wid  = tid >> 5;
    const int wm   = wid % WM;
    const int wn   = wid / WM;
    const int g    = lane >> 2;
    const int t4   = lane & 3;
    const int arow = wm * (BM / WM);
    const int bcol = wn * (BN / WN);

    float acc[2][8][4];
    #pragma unroll
    for (int mi = 0; mi < 2; mi++)
        #pragma unroll
        for (int ni = 0; ni < 8; ni++)
            #pragma unroll
            for (int v = 0; v < 4; v++) acc[mi][ni][v] = 0.f;

    float4 ra[NA];
    float4 rbt[NB];
    float4 rb0[SL], rb1[SL];
    float mxr[NA];
    if (EXPA) {
        #pragma unroll
        for (int u = 0; u < NA; u++)
            mxr[u] = mx[row0 + ((tid + u * 256) >> 2)];
    }

    auto ldgA = [&](int k0) {
        #pragma unroll
        for (int u = 0; u < NA; u++) {
            int i = tid + u * 256;
            int r = i >> 2, k4 = i & 3;
            ra[u] = *(const float4*)(A + (size_t)(row0 + r) * lda + k0 + k4 * 4);
        }
    };
    auto stsA = [&](int buf) {
        #pragma unroll
        for (int u = 0; u < NA; u++) {
            int i = tid + u * 256;
            int r = i >> 2, k4 = i & 3;
            float4 v = ra[u];
            if (EXPA) {
                v.x = __expf(v.x - mxr[u]);
                v.y = __expf(v.y - mxr[u]);
                v.z = __expf(v.z - mxr[u]);
                v.w = __expf(v.w - mxr[u]);
            }
            As[buf][(k4 * 2) * SA + r]     = pk(v.x, v.y);
            As[buf][(k4 * 2 + 1) * SA + r] = pk(v.z, v.w);
        }
    };
    auto ldgB = [&](int k0) {
        if constexpr (TB) {
            #pragma unroll
            for (int u = 0; u < NB; u++) {
                int i = tid + u * 256;
                int n = i >> 2, k4 = i & 3;
                rbt[u] = *(const float4*)(B + (size_t)(col0 + n) * ldb + k0 + k4 * 4);
            }
        } else {
            #pragma unroll
            for (int u = 0; u < SL; u++) {
                int i = tid + u * 256;
                int kp = i / (BN / 4), n4 = i % (BN / 4);
                const float* p = B + (size_t)(k0 + 2 * kp) * ldb + col0 + n4 * 4;
                rb0[u] = *(const float4*)p;
                rb1[u] = *(const float4*)(p + ldb);
            }
        }
    };
    auto stsB = [&](int buf) {
        if constexpr (TB) {
            #pragma unroll
            for (int u = 0; u < NB; u++) {
                int i = tid + u * 256;
                int n = i >> 2, k4 = i & 3;
                Bs[buf][(k4 * 2) * SB + n]     = pk(rbt[u].x, rbt[u].y);
                Bs[buf][(k4 * 2 + 1) * SB + n] = pk(rbt[u].z, rbt[u].w);
            }
        } else {
            #pragma unroll
            for (int u = 0; u < SL; u++) {
                int i = tid + u * 256;
                int kp = i / (BN / 4), n4 = i % (BN / 4);
                uint4 v;
                v.x = pk(rb0[u].x, rb1[u].x);
                v.y = pk(rb0[u].y, rb1[u].y);
                v.z = pk(rb0[u].z, rb1[u].z);
                v.w = pk(rb0[u].w, rb1[u].w);
                *(uint4*)&Bs[buf][kp * SB + n4 * 4] = v;
            }
        }
    };

    ldgA(0); ldgB(0);
    stsA(0); stsB(0);
    __syncthreads();

    const int KT = K / 16;
    for (int kt = 0; kt < KT; kt++) {
        int cur = kt & 1, nxt = cur ^ 1;
        if (kt + 1 < KT) { ldgA((kt + 1) * 16); ldgB((kt + 1) * 16); }

        uint32_t af[2][4], bf[8][2];
        #pragma unroll
        for (int mi = 0; mi < 2; mi++) {
            int mr = arow + mi * 16 + g;
            af[mi][0] = As[cur][t4 * SA + mr];
            af[mi][1] = As[cur][t4 * SA + mr + 8];
            af[mi][2] = As[cur][(t4 + 4) * SA + mr];
            af[mi][3] = As[cur][(t4 + 4) * SA + mr + 8];
        }
        #pragma unroll
        for (int ni = 0; ni < 8; ni++) {
            int nc = bcol + ni * 8 + g;
            bf[ni][0] = Bs[cur][t4 * SB + nc];
            bf[ni][1] = Bs[cur][(t4 + 4) * SB + nc];
        }
        #pragma unroll
        for (int mi = 0; mi < 2; mi++)
            #pragma unroll
            for (int ni = 0; ni < 8; ni++)
                mma16(acc[mi][ni], af[mi], bf[ni]);

        if (kt + 1 < KT) { stsA(nxt); stsB(nxt); }
        __syncthreads();
    }

    // ---- store C ----
    #pragma unroll
    for (int mi = 0; mi < 2; mi++) {
        int r = row0 + arow + mi * 16 + g;
        float s0 = alpha, s1 = alpha;
        if (EXPA) { s0 *= inv[r]; s1 *= inv[r + 8]; }
        float b0 = 0.f, b1 = 0.f;
        if (BIAS) { b0 = bias[r]; b1 = bias[r + 8]; }
        #pragma unroll
        for (int ni = 0; ni < 8; ni++) {
            int c = col0 + bcol + ni * 8 + t4 * 2;
            float2 v0, v1;
            v0.x = s0 * acc[mi][ni][0] + b0;
            v0.y = s0 * acc[mi][ni][1] + b0;
            v1.x = s1 * acc[mi][ni][2] + b1;
            v1.y = s1 * acc[mi][ni][3] + b1;
            *(float2*)&C[(size_t)r * ldc + c]       = v0;
            *(float2*)&C[(size_t)(r + 8) * ldc + c] = v1;
        }
    }

    // ---- fused softmax partial stats (scores GEMM only) ----
    if (STATS) {
        float mrow[2][2];
        #pragma unroll
        for (int mi = 0; mi < 2; mi++)
            #pragma unroll
            for (int hf = 0; hf < 2; hf++) {
                float m = -1e30f;
                #pragma unroll
                for (int ni = 0; ni < 8; ni++)
                    m = fmaxf(m, fmaxf(acc[mi][ni][hf * 2], acc[mi][ni][hf * 2 + 1]));
                m *= alpha;   // alpha > 0
                m = fmaxf(m, __shfl_xor_sync(0xffffffffu, m, 1));
                m = fmaxf(m, __shfl_xor_sync(0xffffffffu, m, 2));
                int rib = arow + mi * 16 + hf * 8 + g;
                if (t4 == 0) redm[wn][rib] = m;
            }
        __syncthreads();
        #pragma unroll
        for (int mi = 0; mi < 2; mi++)
            #pragma unroll
            for (int hf = 0; hf < 2; hf++) {
                int rib = arow + mi * 16 + hf * 8 + g;
                mrow[mi][hf] = fmaxf(redm[0][rib], redm[1][rib]);
            }
        #pragma unroll
        for (int mi = 0; mi < 2; mi++)
            #pragma unroll
            for (int hf = 0; hf < 2; hf++) {
                float m = mrow[mi][hf];
                float s = 0.f;
                #pragma unroll
                for (int ni = 0; ni < 8; ni++) {
                    s += __expf(alpha * acc[mi][ni][hf * 2] - m);
                    s += __expf(alpha * acc[mi][ni][hf * 2 + 1] - m);
                }
                s += __shfl_xor_sync(0xffffffffu, s, 1);
                s += __shfl_xor_sync(0xffffffffu, s, 2);
                int rib = arow + mi * 16 + hf * 8 + g;
                if (t4 == 0) reds[wn][rib] = s;
            }
        __syncthreads();
        if (wn == 0 && t4 == 0) {
            #pragma unroll
            for (int mi = 0; mi < 2; mi++)
                #pragma unroll
                for (int hf = 0; hf < 2; hf++) {
                    int rib = arow + mi * 16 + hf * 8 + g;
                    size_t idx = ((size_t)bz * NBLK + blockIdx.x) * NTOK + row0 + rib;
                    pm[idx] = mrow[mi][hf];
                    ps[idx] = reds[0][rib] + reds[1][rib];
                }
        }
    }
}

// ---------------- combine partial stats -> mx, inv ----------------
__global__ __launch_bounds__(256)
void combine_kernel(const float* __restrict__ pm, const float* __restrict__ ps,
                    float* __restrict__ mx, float* __restrict__ inv)
{
    int r = blockIdx.x * 256 + threadIdx.x;
    int b = blockIdx.y;
    float m = -1e30f;
    for (int cb = 0; cb < NBLK; cb++)
        m = fmaxf(m, pm[((size_t)b * NBLK + cb) * NTOK + r]);
    float s = 0.f;
    for (int cb = 0; cb < NBLK; cb++) {
        size_t idx = ((size_t)b * NBLK + cb) * NTOK + r;
        s += ps[idx] * __expf(pm[idx] - m);
    }
    mx[(size_t)b * NTOK + r]  = m;
    inv[(size_t)b * NTOK + r] = 1.f / s;
}

// ---------------- fp32 GEMM (proj 1x1: accuracy-critical) ----------------
__global__ __launch_bounds__(256)
void gemm128(const float* __restrict__ A, const float* __restrict__ Bm,
             float* __restrict__ Cm,
             int M, int Np, int K, int lda, int ldb, int ldc,
             float alpha, const float* __restrict__ bias,
             size_t sA, size_t sB, size_t sC)
{
    __shared__ float As[8][132];
    __shared__ float Bs[8][132];

    int bz = blockIdx.z;
    A  += (size_t)bz * sA;
    Bm += (size_t)bz * sB;
    Cm += (size_t)bz * sC;

    int tid = threadIdx.x;
    int tx = tid % 16;
    int ty = tid / 16;
    int row0 = blockIdx.y * 128;
    int col0 = blockIdx.x * 128;

    float acc[8][8];
    #pragma unroll
    for (int i = 0; i < 8; i++)
        #pragma unroll
        for (int j = 0; j < 8; j++) acc[i][j] = 0.f;

    int a_k = tid % 8;
    int a_m = (tid / 8) * 4;

    for (int k0 = 0; k0 < K; k0 += 8) {
        #pragma unroll
        for (int j = 0; j < 4; j++) {
            int m = a_m + j;
            int kk = k0 + a_k;
            float v = 0.f;
            if (row0 + m < M && kk < K) v = A[(size_t)(row0 + m) * lda + kk];
            As[a_k][m] = v;
        }
        {
            int b_n  = tid % 128;
            int b_kb = (tid / 128) * 4;
            #pragma unroll
            for (int j = 0; j < 4; j++) {
                int kk = k0 + b_kb + j;
                float v = 0.f;
                if (kk < K && col0 + b_n < Np) v = Bm[(size_t)kk * ldb + col0 + b_n];
                Bs[b_kb + j][b_n] = v;
            }
        }
        __syncthreads();

        #pragma unroll
        for (int kk = 0; kk < 8; kk++) {
            float a[8], b[8];
            #pragma unroll
            for (int i = 0; i < 8; i++) a[i] = As[kk][ty * 8 + i];
            #pragma unroll
            for (int j = 0; j < 8; j++) b[j] = Bs[kk][tx * 8 + j];
            #pragma unroll
            for (int i = 0; i < 8; i++)
                #pragma unroll
                for (int j = 0; j < 8; j++)
                    acc[i][j] += a[i] * b[j];
        }
        __syncthreads();
    }

    #pragma unroll
    for (int i = 0; i < 8; i++) {
        int m = row0 + ty * 8 + i;
        if (m >= M) continue;
        float bv = bias ? bias[m] : 0.f;
        #pragma unroll
        for (int j = 0; j < 8; j++) {
            int n = col0 + tx * 8 + j;
            if (n < Np) Cm[(size_t)m * ldc + n] = alpha * acc[i][j] + bv;
        }
    }
}

// ---------------- pad fuse weights 252 -> 256 K ----------------
__global__ __launch_bounds__(256)
void copyw_kernel(const float* __restrict__ w, float* __restrict__ wp)
{
    int r = blockIdx.x;
    int k = threadIdx.x;
    wp[r * NFPAD + k] = (k < NFEAT) ? w[r * NFEAT + k] : 0.f;
}

// ---------------- reduce ----------------
__global__ __launch_bounds__(256)
void reduce_kernel(const float* __restrict__ fmap, const float* __restrict__ w,
                   const float* __restrict__ bias, float* __restrict__ xr)
{
    __shared__ float ws[INNER * C_DIM];
    int tid = threadIdx.x;
    for (int i = tid; i < INNER * C_DIM; i += 256) ws[i] = w[i];
    __syncthreads();

    int b = blockIdx.y;
    int p = blockIdx.x * 256 + tid;
    const float* fin = fmap + (size_t)b * C_DIM * PIX;
    float acc[INNER];
    #pragma unroll
    for (int o = 0; o < INNER; o++) acc[o] = 0.f;
    for (int ci = 0; ci < C_DIM; ci++) {
        float v = fin[(size_t)ci * PIX + p];
        #pragma unroll
        for (int o = 0; o < INNER; o++) acc[o] += ws[o * C_DIM + ci] * v;
    }
    float* xo = xr + (size_t)b * INNER * PIX;
    #pragma unroll
    for (int o = 0; o < INNER; o++) xo[(size_t)o * PIX + p] = acc[o] + bias[o];
}

// ---------------- dilated 3x3 conv ----------------
__global__ __launch_bounds__(256)
void dilconv_kernel(const float* __restrict__ xr, const float* __restrict__ dw,
                    const float* __restrict__ db, float* __restrict__ conv)
{
    __shared__ float ws[INNER * INNER * 9];
    int i = blockIdx.z;
    int d = i + 1;
    int b = blockIdx.y;
    int tid = threadIdx.x;
    for (int k = tid; k < INNER * INNER * 9; k += 256)
        ws[k] = dw[(size_t)i * INNER * INNER * 9 + k];
    __syncthreads();

    int p = blockIdx.x * 256 + tid;
    int h = p / HW, w = p % HW;
    const float* xin = xr + (size_t)b * INNER * PIX;
    float acc[INNER];
    #pragma unroll
    for (int co = 0; co < INNER; co++) acc[co] = 0.f;

    #pragma unroll
    for (int kh = 0; kh < 3; kh++) {
        int hh = h + (kh - 1) * d;
        if (hh < 0 || hh >= HW) continue;
        #pragma unroll
        for (int kw = 0; kw < 3; kw++) {
            int ww = w + (kw - 1) * d;
            if (ww < 0 || ww >= HW) continue;
            int q = hh * HW + ww;
            for (int ci = 0; ci < INNER; ci++) {
                float v = xin[(size_t)ci * PIX + q];
                int widx = ci * 9 + kh * 3 + kw;
                #pragma unroll
                for (int co = 0; co < INNER; co++)
                    acc[co] += ws[co * (INNER * 9) + widx] * v;
            }
        }
    }
    float* cout = conv + ((size_t)(i * BATCH + b) * INNER) * PIX;
    #pragma unroll
    for (int co = 0; co < INNER; co++)
        cout[(size_t)co * PIX + p] = acc[co] + db[i * INNER + co];
}

// ---------------- feats (+ zero padding channels) ----------------
__global__ __launch_bounds__(256)
void feats_kernel(const float* __restrict__ xr, const float* __restrict__ conv,
                  float* __restrict__ feats)
{
    int b = blockIdx.y;
    int p = blockIdx.x * 256 + threadIdx.x;
    int h = p / HW, w = p % HW;
    const float* xin = xr + (size_t)b * INNER * PIX;
    float* fo = feats + (size_t)b * NFPAD * PIX;

    int q[6];
    q[0] = p;
    q[1] = h * HW + (HW - 1 - w);
    q[2] = (HW - 1 - h) * HW + w;
    q[3] = w * HW + (HW - 1 - h);
    q[4] = (HW - 1 - h) * HW + (HW - 1 - w);
    q[5] = (HW - 1 - w) * HW + h;

    for (int c = 0; c < INNER; c++) {
        float cv[3];
        #pragma unroll
        for (int i = 0; i < 3; i++)
            cv[i] = conv[((size_t)(i * BATCH + b) * INNER + c) * PIX + p];
        float tv[6];
        #pragma unroll
        for (int t = 0; t < 6; t++)
            tv[t] = xin[(size_t)c * PIX + q[t]];
        #pragma unroll
        for (int i = 0; i < 3; i++)
            #pragma unroll
            for (int t = 0; t < 6; t++)
                fo[((size_t)((i * 6 + t) * INNER + c)) * PIX + p] = cv[i] * tv[t];
    }
    #pragma unroll
    for (int f = NFEAT; f < NFPAD; f++)
        fo[(size_t)f * PIX + p] = 0.f;
}

// ---------------- transpose ----------------
__global__ __launch_bounds__(256)
void transpose_kernel(const float* __restrict__ src, float* __restrict__ dst)
{
    __shared__ float tile[32][33];
    int b = blockIdx.z;
    int p0 = blockIdx.x * 32, c0 = blockIdx.y * 32;
    const float* s = src + (size_t)b * C_DIM * PIX;
    float* d = dst + (size_t)b * NTOK * C_DIM;
    int tx = threadIdx.x, ty = threadIdx.y;
    #pragma unroll
    for (int j = 0; j < 32; j += 8)
        tile[ty + j][tx] = s[(size_t)(c0 + ty + j) * PIX + p0 + tx];
    __syncthreads();
    #pragma unroll
    for (int j = 0; j < 32; j += 8)
        d[(size_t)(p0 + ty + j) * C_DIM + c0 + tx] = tile[tx][ty + j];
}

// ---------------- final ----------------
__global__ __launch_bounds__(256)
void final_kernel(const float* __restrict__ fmap, const float* __restrict__ att,
                  float* __restrict__ out)
{
    __shared__ float tile[32][33];
    int b = blockIdx.z;
    int p0 = blockIdx.x * 32, c0 = blockIdx.y * 32;
    int tx = threadIdx.x, ty = threadIdx.y;
    const float* a = att + (size_t)b * NTOK * C_DIM;
    #pragma unroll
    for (int j = 0; j < 32; j += 8)
        tile[ty + j][tx] = a[(size_t)(p0 + ty + j) * C_DIM + c0 + tx];
    __syncthreads();
    const float* f = fmap + (size_t)b * C_DIM * PIX;
    float* o = out + (size_t)b * C_DIM * PIX;
    #pragma unroll
    for (int j = 0; j < 32; j += 8) {
        int c = c0 + ty + j, p = p0 + tx;
        o[(size_t)c * PIX + p] = f[(size_t)c * PIX + p] + 0.2f * tile[tx][ty + j];
    }
}

// ---------------- launch ----------------
extern "C" void kernel_launch(void* const* d_in, const int* in_sizes, int n_in,
                              void* d_out, int out_size)
{
    const float* x        = (const float*)d_in[0];
    const float* proj_w   = (const float*)d_in[1];
    const float* proj_b   = (const float*)d_in[2];
    const float* reduce_w = (const float*)d_in[3];
    const float* reduce_b = (const float*)d_in[4];
    const float* dil_w    = (const float*)d_in[5];
    const float* dil_b    = (const float*)d_in[6];
    const float* fuse_w   = (const float*)d_in[7];
    const float* fuse_b   = (const float*)d_in[8];
    float* out = (float*)d_out;

    void *p_fmap, *p_xr, *p_conv, *p_feats, *p_tokT, *p_tok, *p_scores, *p_att,
         *p_mx, *p_inv, *p_fusew, *p_pm, *p_ps;
    cudaGetSymbolAddress(&p_fmap,   g_fmap);
    cudaGetSymbolAddress(&p_xr,     g_xr);
    cudaGetSymbolAddress(&p_conv,   g_conv);
    cudaGetSymbolAddress(&p_feats,  g_feats);
    cudaGetSymbolAddress(&p_tokT,   g_tokT);
    cudaGetSymbolAddress(&p_tok,    g_tok);
    cudaGetSymbolAddress(&p_scores, g_scores);
    cudaGetSymbolAddress(&p_att,    g_att);
    cudaGetSymbolAddress(&p_mx,     g_mx);
    cudaGetSymbolAddress(&p_inv,    g_inv);
    cudaGetSymbolAddress(&p_fusew,  g_fusew);
    cudaGetSymbolAddress(&p_pm,     g_pm);
    cudaGetSymbolAddress(&p_ps,     g_ps);

    float* fmap   = (float*)p_fmap;
    float* xr     = (float*)p_xr;
    float* conv   = (float*)p_conv;
    float* feats  = (float*)p_feats;
    float* tokT   = (float*)p_tokT;
    float* tok    = (float*)p_tok;
    float* scores = (float*)p_scores;
    float* att    = (float*)p_att;
    float* mx     = (float*)p_mx;
    float* inv    = (float*)p_inv;
    float* fusew  = (float*)p_fusew;
    float* pm     = (float*)p_pm;
    float* ps     = (float*)p_ps;

    // 0) pad fuse weights
    copyw_kernel<<<C_DIM, 256>>>(fuse_w, fusew);

    // 1) proj 1x1 — fp32 (feeds residual directly)
    gemm128<<<dim3(PIX/128, C_DIM/128, BATCH), 256>>>(
        proj_w, x, fmap, C_DIM, PIX, C_DIM, C_DIM, PIX, PIX,
        1.f, proj_b, 0, (size_t)C_DIM*PIX, (size_t)C_DIM*PIX);

    // 2) reduce 1x1
    reduce_kernel<<<dim3(PIX/256, BATCH), 256>>>(fmap, reduce_w, reduce_b, xr);

    // 3) dilated convs
    dilconv_kernel<<<dim3(PIX/256, BATCH, 3), 256>>>(xr, dil_w, dil_b, conv);

    // 4) feats
    feats_kernel<<<dim3(PIX/256, BATCH), 256>>>(xr, conv, feats);

    // 5) fuse 1x1 — fp16 tensor cores
    gemm_f16<128, 128, 4, 2, false, false, true, false>
        <<<dim3(PIX/128, C_DIM/128, BATCH), 256>>>(
        fusew, feats, tokT, NFPAD, NFPAD, PIX, PIX, 1.f,
        fuse_b, nullptr, nullptr, nullptr, nullptr,
        0, (size_t)NFPAD*PIX, (size_t)C_DIM*PIX);

    // 6) transpose -> tok (b,p,c)
    transpose_kernel<<<dim3(PIX/32, C_DIM/32, BATCH), dim3(32, 8)>>>(tokT, tok);

    // 7) scores = (tok @ tok^T)/16 — fp16, with fused softmax partial stats
    gemm_f16<128, 128, 4, 2, true, false, false, true>
        <<<dim3(NBLK, NBLK, BATCH), 256>>>(
        tok, tok, scores, C_DIM, C_DIM, C_DIM, NTOK, 0.0625f,
        nullptr, nullptr, nullptr, pm, ps,
        (size_t)NTOK*C_DIM, (size_t)NTOK*C_DIM, (size_t)NTOK*NTOK);

    // 8) combine partials -> row max + 1/sumexp  (replaces 680MB rowstats read)
    combine_kernel<<<dim3(NTOK/256, BATCH), 256>>>(pm, ps, mx, inv);

    // 9) att = softmax(scores) @ tok — fp16, exp fused into A load
    gemm_f16<64, 256, 2, 4, false, true, false, false>
        <<<dim3(1, NTOK/64, BATCH), 256>>>(
        scores, tok, att, NTOK, NTOK, C_DIM, C_DIM, 1.f,
        nullptr, mx, inv, nullptr, nullptr,
        (size_t)NTOK*NTOK, (size_t)NTOK*C_DIM, (size_t)NTOK*C_DIM);

    // 10) out = fmap + 0.2 * att^T
    final_kernel<<<dim3(PIX/32, C_DIM/32, BATCH), dim3(32, 8)>>>(fmap, att, out);
}

// round 10
// speedup vs baseline: 1.8944x; 1.0708x over previous
#include <cuda_runtime.h>
#include <cuda_fp16.h>
#include <cstdint>
#include <cstddef>

// ---------------- problem constants ----------------
#define BATCH 2
#define C_DIM 256
#define HW 96
#define PIX (HW*HW)          // 9216
#define INNER 14
#define NFEAT (INNER*18)     // 252
#define NFPAD 256
#define NTOK PIX             // 9216
#define NBLK (NTOK/128)      // 72 col-blocks of scores

// ---------------- device scratch ----------------
__device__ float  g_fmap [BATCH * C_DIM * PIX];
__device__ float  g_xr   [BATCH * INNER * PIX];
__device__ float  g_conv [3 * BATCH * INNER * PIX];
__device__ float  g_feats[BATCH * NFPAD * PIX];
__device__ float  g_tokT [BATCH * C_DIM * PIX];
__device__ __half g_tok16[BATCH * NTOK * C_DIM];
__device__ __half g_scores[(size_t)BATCH * NTOK * NTOK];   // fp16: 340MB
__device__ float  g_att  [BATCH * NTOK * C_DIM];
__device__ float  g_mx   [BATCH * NTOK];
__device__ float  g_inv  [BATCH * NTOK];
__device__ float  g_fusew[C_DIM * NFPAD];
__device__ float  g_pm   [(size_t)BATCH * NBLK * NTOK];
__device__ float  g_ps   [(size_t)BATCH * NBLK * NTOK];

// ---------------- fp16 helpers ----------------
__device__ __forceinline__ uint32_t pk(float lo, float hi) {
    uint32_t u;
    asm("cvt.rn.f16x2.f32 %0, %1, %2;" : "=r"(u) : "f"(hi), "f"(lo));
    return u;
}
__device__ __forceinline__ uint32_t h2u(__half2 h) {
    return *reinterpret_cast<uint32_t*>(&h);
}
__device__ __forceinline__ void mma16(float* c, const uint32_t* a, const uint32_t* b) {
    asm volatile(
        "mma.sync.aligned.m16n8k16.row.col.f32.f16.f16.f32 "
        "{%0,%1,%2,%3},{%4,%5,%6,%7},{%8,%9},{%0,%1,%2,%3};"
        : "+f"(c[0]), "+f"(c[1]), "+f"(c[2]), "+f"(c[3])
        : "r"(a[0]), "r"(a[1]), "r"(a[2]), "r"(a[3]), "r"(b[0]), "r"(b[1]));
}

// ---------------- scores: S16 = (tok16 @ tok16^T)/16 + fused stats ----------------
// BM=BN=128, 8 warps (4x2), BK=16, double buffered. A/B loads are raw fp16
// repacks (no conversion). C stored as fp16. Per-colblock softmax partials.
__global__ __launch_bounds__(256, 2)
void scores_f16(const __half* __restrict__ T, __half* __restrict__ S,
                float* __restrict__ pm, float* __restrict__ ps)
{
    constexpr int SA = 136, SB = 136;
    __shared__ uint32_t As[2][8 * SA];
    __shared__ uint32_t Bs[2][8 * SB];
    __shared__ float redm[2][128];
    __shared__ float reds[2][128];

    const int bz = blockIdx.z;
    const __half* Tb = T + (size_t)bz * NTOK * C_DIM;
    __half* Sb = S + (size_t)bz * NTOK * NTOK;

    const int row0 = blockIdx.y * 128;
    const int col0 = blockIdx.x * 128;

    const int tid  = threadIdx.x;
    const int lane = tid & 31;
    const int wid  = tid >> 5;
    const int wm   = wid % 4;
    const int wn   = wid / 4;
    const int g    = lane >> 2;
    const int t4   = lane & 3;
    const int arow = wm * 32;
    const int bcol = wn * 64;

    float acc[2][8][4];
    #pragma unroll
    for (int mi = 0; mi < 2; mi++)
        #pragma unroll
        for (int ni = 0; ni < 8; ni++)
            #pragma unroll
            for (int v = 0; v < 4; v++) acc[mi][ni][v] = 0.f;

    uint2 ra[2], rb[2];
    const int r_ = tid >> 2, seg = tid & 3;       // slot 0
    // slot u: i = tid + u*256 -> r = r_ + 64*u, same seg

    auto ldg = [&](int k0) {
        #pragma unroll
        for (int u = 0; u < 2; u++) {
            int r = r_ + u * 64;
            ra[u] = *(const uint2*)(Tb + (size_t)(row0 + r) * C_DIM + k0 + seg * 4);
            rb[u] = *(const uint2*)(Tb + (size_t)(col0 + r) * C_DIM + k0 + seg * 4);
        }
    };
    auto sts = [&](int buf) {
        #pragma unroll
        for (int u = 0; u < 2; u++) {
            int r = r_ + u * 64;
            As[buf][(seg * 2) * SA + r]     = ra[u].x;
            As[buf][(seg * 2 + 1) * SA + r] = ra[u].y;
            Bs[buf][(seg * 2) * SB + r]     = rb[u].x;
            Bs[buf][(seg * 2 + 1) * SB + r] = rb[u].y;
        }
    };

    ldg(0); sts(0);
    __syncthreads();

    const int KT = C_DIM / 16;
    for (int kt = 0; kt < KT; kt++) {
        int cur = kt & 1, nxt = cur ^ 1;
        if (kt + 1 < KT) ldg((kt + 1) * 16);

        uint32_t af[2][4], bf[8][2];
        #pragma unroll
        for (int mi = 0; mi < 2; mi++) {
            int mr = arow + mi * 16 + g;
            af[mi][0] = As[cur][t4 * SA + mr];
            af[mi][1] = As[cur][t4 * SA + mr + 8];
            af[mi][2] = As[cur][(t4 + 4) * SA + mr];
            af[mi][3] = As[cur][(t4 + 4) * SA + mr + 8];
        }
        #pragma unroll
        for (int ni = 0; ni < 8; ni++) {
            int nc = bcol + ni * 8 + g;
            bf[ni][0] = Bs[cur][t4 * SB + nc];
            bf[ni][1] = Bs[cur][(t4 + 4) * SB + nc];
        }
        #pragma unroll
        for (int mi = 0; mi < 2; mi++)
            #pragma unroll
            for (int ni = 0; ni < 8; ni++)
                mma16(acc[mi][ni], af[mi], bf[ni]);

        if (kt + 1 < KT) sts(nxt);
        __syncthreads();
    }

    const float alpha = 0.0625f;

    // ---- store C (fp16) ----
    #pragma unroll
    for (int mi = 0; mi < 2; mi++) {
        int r = row0 + arow + mi * 16 + g;
        #pragma unroll
        for (int ni = 0; ni < 8; ni++) {
            int c = col0 + bcol + ni * 8 + t4 * 2;
            *(uint32_t*)&Sb[(size_t)r * NTOK + c] =
                pk(alpha * acc[mi][ni][0], alpha * acc[mi][ni][1]);
            *(uint32_t*)&Sb[(size_t)(r + 8) * NTOK + c] =
                pk(alpha * acc[mi][ni][2], alpha * acc[mi][ni][3]);
        }
    }

    // ---- fused softmax partial stats ----
    float mrow[2][2];
    #pragma unroll
    for (int mi = 0; mi < 2; mi++)
        #pragma unroll
        for (int hf = 0; hf < 2; hf++) {
            float m = -1e30f;
            #pragma unroll
            for (int ni = 0; ni < 8; ni++)
                m = fmaxf(m, fmaxf(acc[mi][ni][hf * 2], acc[mi][ni][hf * 2 + 1]));
            m *= alpha;
            m = fmaxf(m, __shfl_xor_sync(0xffffffffu, m, 1));
            m = fmaxf(m, __shfl_xor_sync(0xffffffffu, m, 2));
            int rib = arow + mi * 16 + hf * 8 + g;
            if (t4 == 0) redm[wn][rib] = m;
        }
    __syncthreads();
    #pragma unroll
    for (int mi = 0; mi < 2; mi++)
        #pragma unroll
        for (int hf = 0; hf < 2; hf++) {
            int rib = arow + mi * 16 + hf * 8 + g;
            mrow[mi][hf] = fmaxf(redm[0][rib], redm[1][rib]);
        }
    #pragma unroll
    for (int mi = 0; mi < 2; mi++)
        #pragma unroll
        for (int hf = 0; hf < 2; hf++) {
            float m = mrow[mi][hf];
            float s = 0.f;
            #pragma unroll
            for (int ni = 0; ni < 8; ni++) {
                s += __expf(alpha * acc[mi][ni][hf * 2] - m);
                s += __expf(alpha * acc[mi][ni][hf * 2 + 1] - m);
            }
            s += __shfl_xor_sync(0xffffffffu, s, 1);
            s += __shfl_xor_sync(0xffffffffu, s, 2);
            int rib = arow + mi * 16 + hf * 8 + g;
            if (t4 == 0) reds[wn][rib] = s;
        }
    __syncthreads();
    if (wn == 0 && t4 == 0) {
        #pragma unroll
        for (int mi = 0; mi < 2; mi++)
            #pragma unroll
            for (int hf = 0; hf < 2; hf++) {
                int rib = arow + mi * 16 + hf * 8 + g;
                size_t idx = ((size_t)bz * NBLK + blockIdx.x) * NTOK + row0 + rib;
                pm[idx] = mrow[mi][hf];
                ps[idx] = reds[0][rib] + reds[1][rib];
            }
    }
}

// ---------------- out: att = softmax(S16) @ tok16 ----------------
// BM=64, BN=256 (full C_DIM), 8 warps (2x4), BK=16, double buffered.
// A = fp16 scores, exp(a - mx[row]) on load; epilogue multiplies inv[row].
__global__ __launch_bounds__(256, 2)
void out_f16(const __half* __restrict__ Sc, const __half* __restrict__ T,
             float* __restrict__ att,
             const float* __restrict__ mxp, const float* __restrict__ invp)
{
    constexpr int SA = 72, SB = 264;
    __shared__ uint32_t As[2][8 * SA];
    __shared__ uint32_t Bs[2][8 * SB];

    const int bz = blockIdx.z;
    const __half* Sb = Sc + (size_t)bz * NTOK * NTOK;
    const __half* Tb = T  + (size_t)bz * NTOK * C_DIM;
    float* Cb = att + (size_t)bz * NTOK * C_DIM;
    const float* mx  = mxp  + (size_t)bz * NTOK;
    const float* inv = invp + (size_t)bz * NTOK;

    const int row0 = blockIdx.y * 64;

    const int tid  = threadIdx.x;
    const int lane = tid & 31;
    const int wid  = tid >> 5;
    const int wm   = wid % 2;
    const int wn   = wid / 2;
    const int g    = lane >> 2;
    const int t4   = lane & 3;
    const int arow = wm * 32;
    const int bcol = wn * 64;

    float acc[2][8][4];
    #pragma unroll
    for (int mi = 0; mi < 2; mi++)
        #pragma unroll
        for (int ni = 0; ni < 8; ni++)
            #pragma unroll
            for (int v = 0; v < 4; v++) acc[mi][ni][v] = 0.f;

    // A slot: r = tid>>2 (0..63), seg = tid&3
    const int r_  = tid >> 2, seg = tid & 3;
    const float mxr = mx[row0 + r_];
    // B slot: kp = tid>>5 (0..7), n8 = tid&31 (8 cols each)
    const int kp = tid >> 5, n8 = tid & 31;

    uint2 ra;
    uint4 rb0, rb1;

    auto ldg = [&](int k0) {
        ra = *(const uint2*)(Sb + (size_t)(row0 + r_) * NTOK + k0 + seg * 4);
        const __half* p = Tb + (size_t)(k0 + 2 * kp) * C_DIM + n8 * 8;
        rb0 = *(const uint4*)p;
        rb1 = *(const uint4*)(p + C_DIM);
    };
    auto sts = [&](int buf) {
        __half2 h0 = *reinterpret_cast<__half2*>(&ra.x);
        __half2 h1 = *reinterpret_cast<__half2*>(&ra.y);
        float2 f0 = __half22float2(h0);
        float2 f1 = __half22float2(h1);
        As[buf][(seg * 2) * SA + r_] =
            pk(__expf(f0.x - mxr), __expf(f0.y - mxr));
        As[buf][(seg * 2 + 1) * SA + r_] =
            pk(__expf(f1.x - mxr), __expf(f1.y - mxr));
        const __half2* a2 = reinterpret_cast<const __half2*>(&rb0);
        const __half2* b2 = reinterpret_cast<const __half2*>(&rb1);
        #pragma unroll
        for (int j = 0; j < 4; j++) {
            Bs[buf][kp * SB + n8 * 8 + 2 * j]     = h2u(__lows2half2(a2[j], b2[j]));
            Bs[buf][kp * SB + n8 * 8 + 2 * j + 1] = h2u(__highs2half2(a2[j], b2[j]));
        }
    };

    ldg(0); sts(0);
    __syncthreads();

    const int KT = NTOK / 16;
    for (int kt = 0; kt < KT; kt++) {
        int cur = kt & 1, nxt = cur ^ 1;
        if (kt + 1 < KT) ldg((kt + 1) * 16);

        uint32_t af[2][4], bf[8][2];
        #pragma unroll
        for (int mi = 0; mi < 2; mi++) {
            int mr = arow + mi * 16 + g;
            af[mi][0] = As[cur][t4 * SA + mr];
            af[mi][1] = As[cur][t4 * SA + mr + 8];
            af[mi][2] = As[cur][(t4 + 4) * SA + mr];
            af[mi][3] = As[cur][(t4 + 4) * SA + mr + 8];
        }
        #pragma unroll
        for (int ni = 0; ni < 8; ni++) {
            int nc = bcol + ni * 8 + g;
            bf[ni][0] = Bs[cur][t4 * SB + nc];
            bf[ni][1] = Bs[cur][(t4 + 4) * SB + nc];
        }
        #pragma unroll
        for (int mi = 0; mi < 2; mi++)
            #pragma unroll
            for (int ni = 0; ni < 8; ni++)
                mma16(acc[mi][ni], af[mi], bf[ni]);

        if (kt + 1 < KT) sts(nxt);
        __syncthreads();
    }

    #pragma unroll
    for (int mi = 0; mi < 2; mi++) {
        int r = row0 + arow + mi * 16 + g;
        float s0 = inv[r], s1 = inv[r + 8];
        #pragma unroll
        for (int ni = 0; ni < 8; ni++) {
            int c = bcol + ni * 8 + t4 * 2;
            float2 v0, v1;
            v0.x = s0 * acc[mi][ni][0];
            v0.y = s0 * acc[mi][ni][1];
            v1.x = s1 * acc[mi][ni][2];
            v1.y = s1 * acc[mi][ni][3];
            *(float2*)&Cb[(size_t)r * C_DIM + c]       = v0;
            *(float2*)&Cb[(size_t)(r + 8) * C_DIM + c] = v1;
        }
    }
}

// ---------------- fp16 mma.sync GEMM (fuse 1x1, fp32 in/out) ----------------
__global__ __launch_bounds__(256, 2)
void gemm_f16_fuse(const float* __restrict__ A, const float* __restrict__ B,
                   float* __restrict__ C, const float* __restrict__ bias)
{
    constexpr int SA = 136, SB = 136;
    __shared__ uint32_t As[2][8 * SA];
    __shared__ uint32_t Bs[2][8 * SB];

    const int bz = blockIdx.z;
    B += (size_t)bz * NFPAD * PIX;
    C += (size_t)bz * C_DIM * PIX;

    const int row0 = blockIdx.y * 128;
    const int col0 = blockIdx.x * 128;

    const int tid  = threadIdx.x;
    const int lane = tid & 31;
    const int wid  = tid >> 5;
    const int wm   = wid % 4;
    const int wn   = wid / 4;
    const int g    = lane >> 2;
    const int t4   = lane & 3;
    const int arow = wm * 32;
    const int bcol = wn * 64;

    float acc[2][8][4];
    #pragma unroll
    for (int mi = 0; mi < 2; mi++)
        #pragma unroll
        for (int ni = 0; ni < 8; ni++)
            #pragma unroll
            for (int v = 0; v < 4; v++) acc[mi][ni][v] = 0.f;

    float4 ra[2], rb0, rb1;
    auto ldg = [&](int k0) {
        #pragma unroll
        for (int u = 0; u < 2; u++) {
            int i = tid + u * 256;
            int r = i >> 2, k4 = i & 3;
            ra[u] = *(const float4*)(A + (size_t)(row0 + r) * NFPAD + k0 + k4 * 4);
        }
        int kp = tid / 32, n4 = tid % 32;
        const float* p = B + (size_t)(k0 + 2 * kp) * PIX + col0 + n4 * 4;
        rb0 = *(const float4*)p;
        rb1 = *(const float4*)(p + PIX);
    };
    auto sts = [&](int buf) {
        #pragma unroll
        for (int u = 0; u < 2; u++) {
            int i = tid + u * 256;
            int r = i >> 2, k4 = i & 3;
            As[buf][(k4 * 2) * SA + r]     = pk(ra[u].x, ra[u].y);
            As[buf][(k4 * 2 + 1) * SA + r] = pk(ra[u].z, ra[u].w);
        }
        int kp = tid / 32, n4 = tid % 32;
        uint4 v;
        v.x = pk(rb0.x, rb1.x);
        v.y = pk(rb0.y, rb1.y);
        v.z = pk(rb0.z, rb1.z);
        v.w = pk(rb0.w, rb1.w);
        *(uint4*)&Bs[buf][kp * SB + n4 * 4] = v;
    };

    ldg(0); sts(0);
    __syncthreads();

    const int KT = NFPAD / 16;
    for (int kt = 0; kt < KT; kt++) {
        int cur = kt & 1, nxt = cur ^ 1;
        if (kt + 1 < KT) ldg((kt + 1) * 16);

        uint32_t af[2][4], bf[8][2];
        #pragma unroll
        for (int mi = 0; mi < 2; mi++) {
            int mr = arow + mi * 16 + g;
            af[mi][0] = As[cur][t4 * SA + mr];
            af[mi][1] = As[cur][t4 * SA + mr + 8];
            af[mi][2] = As[cur][(t4 + 4) * SA + mr];
            af[mi][3] = As[cur][(t4 + 4) * SA + mr + 8];
        }
        #pragma unroll
        for (int ni = 0; ni < 8; ni++) {
            int nc = bcol + ni * 8 + g;
            bf[ni][0] = Bs[cur][t4 * SB + nc];
            bf[ni][1] = Bs[cur][(t4 + 4) * SB + nc];
        }
        #pragma unroll
        for (int mi = 0; mi < 2; mi++)
            #pragma unroll
            for (int ni = 0; ni < 8; ni++)
                mma16(acc[mi][ni], af[mi], bf[ni]);

        if (kt + 1 < KT) sts(nxt);
        __syncthreads();
    }

    #pragma unroll
    for (int mi = 0; mi < 2; mi++) {
        int r = row0 + arow + mi * 16 + g;
        float b0 = bias[r], b1 = bias[r + 8];
        #pragma unroll
        for (int ni = 0; ni < 8; ni++) {
            int c = col0 + bcol + ni * 8 + t4 * 2;
            float2 v0, v1;
            v0.x = acc[mi][ni][0] + b0;
            v0.y = acc[mi][ni][1] + b0;
            v1.x = acc[mi][ni][2] + b1;
            v1.y = acc[mi][ni][3] + b1;
            *(float2*)&C[(size_t)r * PIX + c]       = v0;
            *(float2*)&C[(size_t)(r + 8) * PIX + c] = v1;
        }
    }
}

// ---------------- combine partial stats -> mx, inv ----------------
__global__ __launch_bounds__(256)
void combine_kernel(const float* __restrict__ pm, const float* __restrict__ ps,
                    float* __restrict__ mx, float* __restrict__ inv)
{
    int r = blockIdx.x * 256 + threadIdx.x;
    int b = blockIdx.y;
    float m = -1e30f;
    for (int cb = 0; cb < NBLK; cb++)
        m = fmaxf(m, pm[((size_t)b * NBLK + cb) * NTOK + r]);
    float s = 0.f;
    for (int cb = 0; cb < NBLK; cb++) {
        size_t idx = ((size_t)b * NBLK + cb) * NTOK + r;
        s += ps[idx] * __expf(pm[idx] - m);
    }
    mx[(size_t)b * NTOK + r]  = m;
    inv[(size_t)b * NTOK + r] = 1.f / s;
}

// ---------------- fp32 GEMM (proj 1x1) ----------------
__global__ __launch_bounds__(256)
void gemm128(const float* __restrict__ A, const float* __restrict__ Bm,
             float* __restrict__ Cm,
             int M, int Np, int K, int lda, int ldb, int ldc,
             float alpha, const float* __restrict__ bias,
             size_t sA, size_t sB, size_t sC)
{
    __shared__ float As[8][132];
    __shared__ float Bs[8][132];

    int bz = blockIdx.z;
    A  += (size_t)bz * sA;
    Bm += (size_t)bz * sB;
    Cm += (size_t)bz * sC;

    int tid = threadIdx.x;
    int tx = tid % 16;
    int ty = tid / 16;
    int row0 = blockIdx.y * 128;
    int col0 = blockIdx.x * 128;

    float acc[8][8];
    #pragma unroll
    for (int i = 0; i < 8; i++)
        #pragma unroll
        for (int j = 0; j < 8; j++) acc[i][j] = 0.f;

    int a_k = tid % 8;
    int a_m = (tid / 8) * 4;

    for (int k0 = 0; k0 < K; k0 += 8) {
        #pragma unroll
        for (int j = 0; j < 4; j++) {
            int m = a_m + j;
            int kk = k0 + a_k;
            float v = 0.f;
            if (row0 + m < M && kk < K) v = A[(size_t)(row0 + m) * lda + kk];
            As[a_k][m] = v;
        }
        {
            int b_n  = tid % 128;
            int b_kb = (tid / 128) * 4;
            #pragma unroll
            for (int j = 0; j < 4; j++) {
                int kk = k0 + b_kb + j;
                float v = 0.f;
                if (kk < K && col0 + b_n < Np) v = Bm[(size_t)kk * ldb + col0 + b_n];
                Bs[b_kb + j][b_n] = v;
            }
        }
        __syncthreads();

        #pragma unroll
        for (int kk = 0; kk < 8; kk++) {
            float a[8], b[8];
            #pragma unroll
            for (int i = 0; i < 8; i++) a[i] = As[kk][ty * 8 + i];
            #pragma unroll
            for (int j = 0; j < 8; j++) b[j] = Bs[kk][tx * 8 + j];
            #pragma unroll
            for (int i = 0; i < 8; i++)
                #pragma unroll
                for (int j = 0; j < 8; j++)
                    acc[i][j] += a[i] * b[j];
        }
        __syncthreads();
    }

    #pragma unroll
    for (int i = 0; i < 8; i++) {
        int m = row0 + ty * 8 + i;
        if (m >= M) continue;
        float bv = bias ? bias[m] : 0.f;
        #pragma unroll
        for (int j = 0; j < 8; j++) {
            int n = col0 + tx * 8 + j;
            if (n < Np) Cm[(size_t)m * ldc + n] = alpha * acc[i][j] + bv;
        }
    }
}

// ---------------- pad fuse weights ----------------
__global__ __launch_bounds__(256)
void copyw_kernel(const float* __restrict__ w, float* __restrict__ wp)
{
    int r = blockIdx.x;
    int k = threadIdx.x;
    wp[r * NFPAD + k] = (k < NFEAT) ? w[r * NFEAT + k] : 0.f;
}

// ---------------- reduce ----------------
__global__ __launch_bounds__(256)
void reduce_kernel(const float* __restrict__ fmap, const float* __restrict__ w,
                   const float* __restrict__ bias, float* __restrict__ xr)
{
    __shared__ float ws[INNER * C_DIM];
    int tid = threadIdx.x;
    for (int i = tid; i < INNER * C_DIM; i += 256) ws[i] = w[i];
    __syncthreads();

    int b = blockIdx.y;
    int p = blockIdx.x * 256 + tid;
    const float* fin = fmap + (size_t)b * C_DIM * PIX;
    float acc[INNER];
    #pragma unroll
    for (int o = 0; o < INNER; o++) acc[o] = 0.f;
    for (int ci = 0; ci < C_DIM; ci++) {
        float v = fin[(size_t)ci * PIX + p];
        #pragma unroll
        for (int o = 0; o < INNER; o++) acc[o] += ws[o * C_DIM + ci] * v;
    }
    float* xo = xr + (size_t)b * INNER * PIX;
    #pragma unroll
    for (int o = 0; o < INNER; o++) xo[(size_t)o * PIX + p] = acc[o] + bias[o];
}

// ---------------- dilated 3x3 conv ----------------
__global__ __launch_bounds__(256)
void dilconv_kernel(const float* __restrict__ xr, const float* __restrict__ dw,
                    const float* __restrict__ db, float* __restrict__ conv)
{
    __shared__ float ws[INNER * INNER * 9];
    int i = blockIdx.z;
    int d = i + 1;
    int b = blockIdx.y;
    int tid = threadIdx.x;
    for (int k = tid; k < INNER * INNER * 9; k += 256)
        ws[k] = dw[(size_t)i * INNER * INNER * 9 + k];
    __syncthreads();

    int p = blockIdx.x * 256 + tid;
    int h = p / HW, w = p % HW;
    const float* xin = xr + (size_t)b * INNER * PIX;
    float acc[INNER];
    #pragma unroll
    for (int co = 0; co < INNER; co++) acc[co] = 0.f;

    #pragma unroll
    for (int kh = 0; kh < 3; kh++) {
        int hh = h + (kh - 1) * d;
        if (hh < 0 || hh >= HW) continue;
        #pragma unroll
        for (int kw = 0; kw < 3; kw++) {
            int ww = w + (kw - 1) * d;
            if (ww < 0 || ww >= HW) continue;
            int q = hh * HW + ww;
            for (int ci = 0; ci < INNER; ci++) {
                float v = xin[(size_t)ci * PIX + q];
                int widx = ci * 9 + kh * 3 + kw;
                #pragma unroll
                for (int co = 0; co < INNER; co++)
                    acc[co] += ws[co * (INNER * 9) + widx] * v;
            }
        }
    }
    float* cout = conv + ((size_t)(i * BATCH + b) * INNER) * PIX;
    #pragma unroll
    for (int co = 0; co < INNER; co++)
        cout[(size_t)co * PIX + p] = acc[co] + db[i * INNER + co];
}

// ---------------- feats ----------------
__global__ __launch_bounds__(256)
void feats_kernel(const float* __restrict__ xr, const float* __restrict__ conv,
                  float* __restrict__ feats)
{
    int b = blockIdx.y;
    int p = blockIdx.x * 256 + threadIdx.x;
    int h = p / HW, w = p % HW;
    const float* xin = xr + (size_t)b * INNER * PIX;
    float* fo = feats + (size_t)b * NFPAD * PIX;

    int q[6];
    q[0] = p;
    q[1] = h * HW + (HW - 1 - w);
    q[2] = (HW - 1 - h) * HW + w;
    q[3] = w * HW + (HW - 1 - h);
    q[4] = (HW - 1 - h) * HW + (HW - 1 - w);
    q[5] = (HW - 1 - w) * HW + h;

    for (int c = 0; c < INNER; c++) {
        float cv[3];
        #pragma unroll
        for (int i = 0; i < 3; i++)
            cv[i] = conv[((size_t)(i * BATCH + b) * INNER + c) * PIX + p];
        float tv[6];
        #pragma unroll
        for (int t = 0; t < 6; t++)
            tv[t] = xin[(size_t)c * PIX + q[t]];
        #pragma unroll
        for (int i = 0; i < 3; i++)
            #pragma unroll
            for (int t = 0; t < 6; t++)
                fo[((size_t)((i * 6 + t) * INNER + c)) * PIX + p] = cv[i] * tv[t];
    }
    #pragma unroll
    for (int f = NFEAT; f < NFPAD; f++)
        fo[(size_t)f * PIX + p] = 0.f;
}

// ---------------- transpose: (b,c,p) -> (b,p,c) fp16 ----------------
__global__ __launch_bounds__(256)
void transpose_kernel(const float* __restrict__ src, __half* __restrict__ dst16)
{
    __shared__ float tile[32][33];
    int b = blockIdx.z;
    int p0 = blockIdx.x * 32, c0 = blockIdx.y * 32;
    const float* s = src + (size_t)b * C_DIM * PIX;
    __half* d16 = dst16 + (size_t)b * NTOK * C_DIM;
    int tx = threadIdx.x, ty = threadIdx.y;
    #pragma unroll
    for (int j = 0; j < 32; j += 8)
        tile[ty + j][tx] = s[(size_t)(c0 + ty + j) * PIX + p0 + tx];
    __syncthreads();
    #pragma unroll
    for (int j = 0; j < 32; j += 8)
        d16[(size_t)(p0 + ty + j) * C_DIM + c0 + tx] = __float2half(tile[tx][ty + j]);
}

// ---------------- final ----------------
__global__ __launch_bounds__(256)
void final_kernel(const float* __restrict__ fmap, const float* __restrict__ att,
                  float* __restrict__ out)
{
    __shared__ float tile[32][33];
    int b = blockIdx.z;
    int p0 = blockIdx.x * 32, c0 = blockIdx.y * 32;
    int tx = threadIdx.x, ty = threadIdx.y;
    const float* a = att + (size_t)b * NTOK * C_DIM;
    #pragma unroll
    for (int j = 0; j < 32; j += 8)
        tile[ty + j][tx] = a[(size_t)(p0 + ty + j) * C_DIM + c0 + tx];
    __syncthreads();
    const float* f = fmap + (size_t)b * C_DIM * PIX;
    float* o = out + (size_t)b * C_DIM * PIX;
    #pragma unroll
    for (int j = 0; j < 32; j += 8) {
        int c = c0 + ty + j, p = p0 + tx;
        o[(size_t)c * PIX + p] = f[(size_t)c * PIX + p] + 0.2f * tile[tx][ty + j];
    }
}

// ---------------- launch ----------------
extern "C" void kernel_launch(void* const* d_in, const int* in_sizes, int n_in,
                              void* d_out, int out_size)
{
    const float* x        = (const float*)d_in[0];
    const float* proj_w   = (const float*)d_in[1];
    const float* proj_b   = (const float*)d_in[2];
    const float* reduce_w = (const float*)d_in[3];
    const float* reduce_b = (const float*)d_in[4];
    const float* dil_w    = (const float*)d_in[5];
    const float* dil_b    = (const float*)d_in[6];
    const float* fuse_w   = (const float*)d_in[7];
    const float* fuse_b   = (const float*)d_in[8];
    float* out = (float*)d_out;

    void *p_fmap, *p_xr, *p_conv, *p_feats, *p_tokT, *p_tok16,
         *p_scores, *p_att, *p_mx, *p_inv, *p_fusew, *p_pm, *p_ps;
    cudaGetSymbolAddress(&p_fmap,   g_fmap);
    cudaGetSymbolAddress(&p_xr,     g_xr);
    cudaGetSymbolAddress(&p_conv,   g_conv);
    cudaGetSymbolAddress(&p_feats,  g_feats);
    cudaGetSymbolAddress(&p_tokT,   g_tokT);
    cudaGetSymbolAddress(&p_tok16,  g_tok16);
    cudaGetSymbolAddress(&p_scores, g_scores);
    cudaGetSymbolAddress(&p_att,    g_att);
    cudaGetSymbolAddress(&p_mx,     g_mx);
    cudaGetSymbolAddress(&p_inv,    g_inv);
    cudaGetSymbolAddress(&p_fusew,  g_fusew);
    cudaGetSymbolAddress(&p_pm,     g_pm);
    cudaGetSymbolAddress(&p_ps,     g_ps);

    float*  fmap   = (float*)p_fmap;
    float*  xr     = (float*)p_xr;
    float*  conv   = (float*)p_conv;
    float*  feats  = (float*)p_feats;
    float*  tokT   = (float*)p_tokT;
    __half* tok16  = (__half*)p_tok16;
    __half* scores = (__half*)p_scores;
    float*  att    = (float*)p_att;
    float*  mx     = (float*)p_mx;
    float*  inv    = (float*)p_inv;
    float*  fusew  = (float*)p_fusew;
    float*  pm     = (float*)p_pm;
    float*  ps     = (float*)p_ps;

    // 0) pad fuse weights
    copyw_kernel<<<C_DIM, 256>>>(fuse_w, fusew);

    // 1) proj 1x1 — fp32 (feeds residual directly)
    gemm128<<<dim3(PIX/128, C_DIM/128, BATCH), 256>>>(
        proj_w, x, fmap, C_DIM, PIX, C_DIM, C_DIM, PIX, PIX,
        1.f, proj_b, 0, (size_t)C_DIM*PIX, (size_t)C_DIM*PIX);

    // 2) reduce 1x1
    reduce_kernel<<<dim3(PIX/256, BATCH), 256>>>(fmap, reduce_w, reduce_b, xr);

    // 3) dilated convs
    dilconv_kernel<<<dim3(PIX/256, BATCH, 3), 256>>>(xr, dil_w, dil_b, conv);

    // 4) feats
    feats_kernel<<<dim3(PIX/256, BATCH), 256>>>(xr, conv, feats);

    // 5) fuse 1x1 — fp16 mma.sync
    gemm_f16_fuse<<<dim3(PIX/128, C_DIM/128, BATCH), 256>>>(
        fusew, feats, tokT, fuse_b);

    // 6) transpose -> tok16 (b,p,c) fp16 only
    transpose_kernel<<<dim3(PIX/32, C_DIM/32, BATCH), dim3(32, 8)>>>(tokT, tok16);

    // 7) scores (fp16 out) + fused softmax partial stats
    scores_f16<<<dim3(NBLK, NBLK, BATCH), 256>>>(tok16, scores, pm, ps);

    // 8) combine partials
    combine_kernel<<<dim3(NTOK/256, BATCH), 256>>>(pm, ps, mx, inv);

    // 9) att = softmax(scores) @ tok16 — exp fused into A load
    out_f16<<<dim3(1, NTOK/64, BATCH), 256>>>(scores, tok16, att, mx, inv);

    // 10) out = fmap + 0.2 * att^T
    final_kernel<<<dim3(PIX/32, C_DIM/32, BATCH), dim3(32, 8)>>>(fmap, att, out);
}

// round 11
// speedup vs baseline: 1.9058x; 1.0061x over previous
#include <cuda_runtime.h>
#include <cuda_fp16.h>
#include <cstdint>
#include <cstddef>

// ---------------- problem constants ----------------
#define BATCH 2
#define C_DIM 256
#define HW 96
#define PIX (HW*HW)          // 9216
#define INNER 14
#define NFEAT (INNER*18)     // 252
#define NFPAD 256
#define NTOK PIX             // 9216
#define NBLK (NTOK/128)      // 72 col-blocks of scores

// ---------------- device scratch ----------------
__device__ float  g_fmap [BATCH * C_DIM * PIX];
__device__ float  g_xr   [BATCH * INNER * PIX];
__device__ float  g_conv [3 * BATCH * INNER * PIX];
__device__ float  g_feats[BATCH * NFPAD * PIX];
__device__ float  g_tokT [BATCH * C_DIM * PIX];
__device__ __half g_tok16[BATCH * NTOK * C_DIM];
__device__ __half g_scores[(size_t)BATCH * NTOK * NTOK];   // fp16: 340MB
__device__ float  g_att  [BATCH * NTOK * C_DIM];
__device__ float  g_mx   [BATCH * NTOK];
__device__ float  g_inv  [BATCH * NTOK];
__device__ float  g_fusew[C_DIM * NFPAD];
__device__ float  g_pm   [(size_t)BATCH * NBLK * NTOK];
__device__ float  g_ps   [(size_t)BATCH * NBLK * NTOK];

// ---------------- fp16 helpers ----------------
__device__ __forceinline__ uint32_t pk(float lo, float hi) {
    uint32_t u;
    asm("cvt.rn.f16x2.f32 %0, %1, %2;" : "=r"(u) : "f"(hi), "f"(lo));
    return u;
}
__device__ __forceinline__ uint32_t h2u(__half2 h) {
    return *reinterpret_cast<uint32_t*>(&h);
}
__device__ __forceinline__ void mma16(float* c, const uint32_t* a, const uint32_t* b) {
    asm volatile(
        "mma.sync.aligned.m16n8k16.row.col.f32.f16.f16.f32 "
        "{%0,%1,%2,%3},{%4,%5,%6,%7},{%8,%9},{%0,%1,%2,%3};"
        : "+f"(c[0]), "+f"(c[1]), "+f"(c[2]), "+f"(c[3])
        : "r"(a[0]), "r"(a[1]), "r"(a[2]), "r"(a[3]), "r"(b[0]), "r"(b[1]));
}

// ---------------- scores: S16 = (tok16 @ tok16^T)/16 + fused stats ----------------
// BM=BN=128, 8 warps (4x2), BK=16, double buffered. A/B loads are raw fp16
// repacks (no conversion). C stored as fp16. Per-colblock softmax partials.
__global__ __launch_bounds__(256, 2)
void scores_f16(const __half* __restrict__ T, __half* __restrict__ S,
                float* __restrict__ pm, float* __restrict__ ps)
{
    constexpr int SA = 136, SB = 136;
    __shared__ uint32_t As[2][8 * SA];
    __shared__ uint32_t Bs[2][8 * SB];
    __shared__ float redm[2][128];
    __shared__ float reds[2][128];

    const int bz = blockIdx.z;
    const __half* Tb = T + (size_t)bz * NTOK * C_DIM;
    __half* Sb = S + (size_t)bz * NTOK * NTOK;

    const int row0 = blockIdx.y * 128;
    const int col0 = blockIdx.x * 128;

    const int tid  = threadIdx.x;
    const int lane = tid & 31;
    const int wid  = tid >> 5;
    const int wm   = wid % 4;
    const int wn   = wid / 4;
    const int g    = lane >> 2;
    const int t4   = lane & 3;
    const int arow = wm * 32;
    const int bcol = wn * 64;

    float acc[2][8][4];
    #pragma unroll
    for (int mi = 0; mi < 2; mi++)
        #pragma unroll
        for (int ni = 0; ni < 8; ni++)
            #pragma unroll
            for (int v = 0; v < 4; v++) acc[mi][ni][v] = 0.f;

    uint2 ra[2], rb[2];
    const int r_ = tid >> 2, seg = tid & 3;       // slot 0
    // slot u: i = tid + u*256 -> r = r_ + 64*u, same seg

    auto ldg = [&](int k0) {
        #pragma unroll
        for (int u = 0; u < 2; u++) {
            int r = r_ + u * 64;
            ra[u] = *(const uint2*)(Tb + (size_t)(row0 + r) * C_DIM + k0 + seg * 4);
            rb[u] = *(const uint2*)(Tb + (size_t)(col0 + r) * C_DIM + k0 + seg * 4);
        }
    };
    auto sts = [&](int buf) {
        #pragma unroll
        for (int u = 0; u < 2; u++) {
            int r = r_ + u * 64;
            As[buf][(seg * 2) * SA + r]     = ra[u].x;
            As[buf][(seg * 2 + 1) * SA + r] = ra[u].y;
            Bs[buf][(seg * 2) * SB + r]     = rb[u].x;
            Bs[buf][(seg * 2 + 1) * SB + r] = rb[u].y;
        }
    };

    ldg(0); sts(0);
    __syncthreads();

    const int KT = C_DIM / 16;
    for (int kt = 0; kt < KT; kt++) {
        int cur = kt & 1, nxt = cur ^ 1;
        if (kt + 1 < KT) ldg((kt + 1) * 16);

        uint32_t af[2][4], bf[8][2];
        #pragma unroll
        for (int mi = 0; mi < 2; mi++) {
            int mr = arow + mi * 16 + g;
            af[mi][0] = As[cur][t4 * SA + mr];
            af[mi][1] = As[cur][t4 * SA + mr + 8];
            af[mi][2] = As[cur][(t4 + 4) * SA + mr];
            af[mi][3] = As[cur][(t4 + 4) * SA + mr + 8];
        }
        #pragma unroll
        for (int ni = 0; ni < 8; ni++) {
            int nc = bcol + ni * 8 + g;
            bf[ni][0] = Bs[cur][t4 * SB + nc];
            bf[ni][1] = Bs[cur][(t4 + 4) * SB + nc];
        }
        #pragma unroll
        for (int mi = 0; mi < 2; mi++)
            #pragma unroll
            for (int ni = 0; ni < 8; ni++)
                mma16(acc[mi][ni], af[mi], bf[ni]);

        if (kt + 1 < KT) sts(nxt);
        __syncthreads();
    }

    const float alpha = 0.0625f;

    // ---- store C (fp16) ----
    #pragma unroll
    for (int mi = 0; mi < 2; mi++) {
        int r = row0 + arow + mi * 16 + g;
        #pragma unroll
        for (int ni = 0; ni < 8; ni++) {
            int c = col0 + bcol + ni * 8 + t4 * 2;
            *(uint32_t*)&Sb[(size_t)r * NTOK + c] =
                pk(alpha * acc[mi][ni][0], alpha * acc[mi][ni][1]);
            *(uint32_t*)&Sb[(size_t)(r + 8) * NTOK + c] =
                pk(alpha * acc[mi][ni][2], alpha * acc[mi][ni][3]);
        }
    }

    // ---- fused softmax partial stats ----
    float mrow[2][2];
    #pragma unroll
    for (int mi = 0; mi < 2; mi++)
        #pragma unroll
        for (int hf = 0; hf < 2; hf++) {
            float m = -1e30f;
            #pragma unroll
            for (int ni = 0; ni < 8; ni++)
                m = fmaxf(m, fmaxf(acc[mi][ni][hf * 2], acc[mi][ni][hf * 2 + 1]));
            m *= alpha;
            m = fmaxf(m, __shfl_xor_sync(0xffffffffu, m, 1));
            m = fmaxf(m, __shfl_xor_sync(0xffffffffu, m, 2));
            int rib = arow + mi * 16 + hf * 8 + g;
            if (t4 == 0) redm[wn][rib] = m;
        }
    __syncthreads();
    #pragma unroll
    for (int mi = 0; mi < 2; mi++)
        #pragma unroll
        for (int hf = 0; hf < 2; hf++) {
            int rib = arow + mi * 16 + hf * 8 + g;
            mrow[mi][hf] = fmaxf(redm[0][rib], redm[1][rib]);
        }
    #pragma unroll
    for (int mi = 0; mi < 2; mi++)
        #pragma unroll
        for (int hf = 0; hf < 2; hf++) {
            float m = mrow[mi][hf];
            float s = 0.f;
            #pragma unroll
            for (int ni = 0; ni < 8; ni++) {
                s += __expf(alpha * acc[mi][ni][hf * 2] - m);
                s += __expf(alpha * acc[mi][ni][hf * 2 + 1] - m);
            }
            s += __shfl_xor_sync(0xffffffffu, s, 1);
            s += __shfl_xor_sync(0xffffffffu, s, 2);
            int rib = arow + mi * 16 + hf * 8 + g;
            if (t4 == 0) reds[wn][rib] = s;
        }
    __syncthreads();
    if (wn == 0 && t4 == 0) {
        #pragma unroll
        for (int mi = 0; mi < 2; mi++)
            #pragma unroll
            for (int hf = 0; hf < 2; hf++) {
                int rib = arow + mi * 16 + hf * 8 + g;
                size_t idx = ((size_t)bz * NBLK + blockIdx.x) * NTOK + row0 + rib;
                pm[idx] = mrow[mi][hf];
                ps[idx] = reds[0][rib] + reds[1][rib];
            }
    }
}

// ---------------- out: att = softmax(S16) @ tok16 ----------------
// BM=64, BN=256 (full C_DIM), 8 warps (2x4), BK=16, double buffered.
// A = fp16 scores, exp(a - mx[row]) on load; epilogue multiplies inv[row].
__global__ __launch_bounds__(256, 2)
void out_f16(const __half* __restrict__ Sc, const __half* __restrict__ T,
             float* __restrict__ att,
             const float* __restrict__ mxp, const float* __restrict__ invp)
{
    constexpr int SA = 72, SB = 264;
    __shared__ uint32_t As[2][8 * SA];
    __shared__ uint32_t Bs[2][8 * SB];

    const int bz = blockIdx.z;
    const __half* Sb = Sc + (size_t)bz * NTOK * NTOK;
    const __half* Tb = T  + (size_t)bz * NTOK * C_DIM;
    float* Cb = att + (size_t)bz * NTOK * C_DIM;
    const float* mx  = mxp  + (size_t)bz * NTOK;
    const float* inv = invp + (size_t)bz * NTOK;

    const int row0 = blockIdx.y * 64;

    const int tid  = threadIdx.x;
    const int lane = tid & 31;
    const int wid  = tid >> 5;
    const int wm   = wid % 2;
    const int wn   = wid / 2;
    const int g    = lane >> 2;
    const int t4   = lane & 3;
    const int arow = wm * 32;
    const int bcol = wn * 64;

    float acc[2][8][4];
    #pragma unroll
    for (int mi = 0; mi < 2; mi++)
        #pragma unroll
        for (int ni = 0; ni < 8; ni++)
            #pragma unroll
            for (int v = 0; v < 4; v++) acc[mi][ni][v] = 0.f;

    // A slot: r = tid>>2 (0..63), seg = tid&3
    const int r_  = tid >> 2, seg = tid & 3;
    const float mxr = mx[row0 + r_];
    // B slot: kp = tid>>5 (0..7), n8 = tid&31 (8 cols each)
    const int kp = tid >> 5, n8 = tid & 31;

    uint2 ra;
    uint4 rb0, rb1;

    auto ldg = [&](int k0) {
        ra = *(const uint2*)(Sb + (size_t)(row0 + r_) * NTOK + k0 + seg * 4);
        const __half* p = Tb + (size_t)(k0 + 2 * kp) * C_DIM + n8 * 8;
        rb0 = *(const uint4*)p;
        rb1 = *(const uint4*)(p + C_DIM);
    };
    auto sts = [&](int buf) {
        __half2 h0 = *reinterpret_cast<__half2*>(&ra.x);
        __half2 h1 = *reinterpret_cast<__half2*>(&ra.y);
        float2 f0 = __half22float2(h0);
        float2 f1 = __half22float2(h1);
        As[buf][(seg * 2) * SA + r_] =
            pk(__expf(f0.x - mxr), __expf(f0.y - mxr));
        As[buf][(seg * 2 + 1) * SA + r_] =
            pk(__expf(f1.x - mxr), __expf(f1.y - mxr));
        const __half2* a2 = reinterpret_cast<const __half2*>(&rb0);
        const __half2* b2 = reinterpret_cast<const __half2*>(&rb1);
        #pragma unroll
        for (int j = 0; j < 4; j++) {
            Bs[buf][kp * SB + n8 * 8 + 2 * j]     = h2u(__lows2half2(a2[j], b2[j]));
            Bs[buf][kp * SB + n8 * 8 + 2 * j + 1] = h2u(__highs2half2(a2[j], b2[j]));
        }
    };

    ldg(0); sts(0);
    __syncthreads();

    const int KT = NTOK / 16;
    for (int kt = 0; kt < KT; kt++) {
        int cur = kt & 1, nxt = cur ^ 1;
        if (kt + 1 < KT) ldg((kt + 1) * 16);

        uint32_t af[2][4], bf[8][2];
        #pragma unroll
        for (int mi = 0; mi < 2; mi++) {
            int mr = arow + mi * 16 + g;
            af[mi][0] = As[cur][t4 * SA + mr];
            af[mi][1] = As[cur][t4 * SA + mr + 8];
            af[mi][2] = As[cur][(t4 + 4) * SA + mr];
            af[mi][3] = As[cur][(t4 + 4) * SA + mr + 8];
        }
        #pragma unroll
        for (int ni = 0; ni < 8; ni++) {
            int nc = bcol + ni * 8 + g;
            bf[ni][0] = Bs[cur][t4 * SB + nc];
            bf[ni][1] = Bs[cur][(t4 + 4) * SB + nc];
        }
        #pragma unroll
        for (int mi = 0; mi < 2; mi++)
            #pragma unroll
            for (int ni = 0; ni < 8; ni++)
                mma16(acc[mi][ni], af[mi], bf[ni]);

        if (kt + 1 < KT) sts(nxt);
        __syncthreads();
    }

    #pragma unroll
    for (int mi = 0; mi < 2; mi++) {
        int r = row0 + arow + mi * 16 + g;
        float s0 = inv[r], s1 = inv[r + 8];
        #pragma unroll
        for (int ni = 0; ni < 8; ni++) {
            int c = bcol + ni * 8 + t4 * 2;
            float2 v0, v1;
            v0.x = s0 * acc[mi][ni][0];
            v0.y = s0 * acc[mi][ni][1];
            v1.x = s1 * acc[mi][ni][2];
            v1.y = s1 * acc[mi][ni][3];
            *(float2*)&Cb[(size_t)r * C_DIM + c]       = v0;
            *(float2*)&Cb[(size_t)(r + 8) * C_DIM + c] = v1;
        }
    }
}

// ---------------- fp16 mma.sync GEMM (fuse 1x1, fp32 in/out) ----------------
__global__ __launch_bounds__(256, 2)
void gemm_f16_fuse(const float* __restrict__ A, const float* __restrict__ B,
                   float* __restrict__ C, const float* __restrict__ bias)
{
    constexpr int SA = 136, SB = 136;
    __shared__ uint32_t As[2][8 * SA];
    __shared__ uint32_t Bs[2][8 * SB];

    const int bz = blockIdx.z;
    B += (size_t)bz * NFPAD * PIX;
    C += (size_t)bz * C_DIM * PIX;

    const int row0 = blockIdx.y * 128;
    const int col0 = blockIdx.x * 128;

    const int tid  = threadIdx.x;
    const int lane = tid & 31;
    const int wid  = tid >> 5;
    const int wm   = wid % 4;
    const int wn   = wid / 4;
    const int g    = lane >> 2;
    const int t4   = lane & 3;
    const int arow = wm * 32;
    const int bcol = wn * 64;

    float acc[2][8][4];
    #pragma unroll
    for (int mi = 0; mi < 2; mi++)
        #pragma unroll
        for (int ni = 0; ni < 8; ni++)
            #pragma unroll
            for (int v = 0; v < 4; v++) acc[mi][ni][v] = 0.f;

    float4 ra[2], rb0, rb1;
    auto ldg = [&](int k0) {
        #pragma unroll
        for (int u = 0; u < 2; u++) {
            int i = tid + u * 256;
            int r = i >> 2, k4 = i & 3;
            ra[u] = *(const float4*)(A + (size_t)(row0 + r) * NFPAD + k0 + k4 * 4);
        }
        int kp = tid / 32, n4 = tid % 32;
        const float* p = B + (size_t)(k0 + 2 * kp) * PIX + col0 + n4 * 4;
        rb0 = *(const float4*)p;
        rb1 = *(const float4*)(p + PIX);
    };
    auto sts = [&](int buf) {
        #pragma unroll
        for (int u = 0; u < 2; u++) {
            int i = tid + u * 256;
            int r = i >> 2, k4 = i & 3;
            As[buf][(k4 * 2) * SA + r]     = pk(ra[u].x, ra[u].y);
            As[buf][(k4 * 2 + 1) * SA + r] = pk(ra[u].z, ra[u].w);
        }
        int kp = tid / 32, n4 = tid % 32;
        uint4 v;
        v.x = pk(rb0.x, rb1.x);
        v.y = pk(rb0.y, rb1.y);
        v.z = pk(rb0.z, rb1.z);
        v.w = pk(rb0.w, rb1.w);
        *(uint4*)&Bs[buf][kp * SB + n4 * 4] = v;
    };

    ldg(0); sts(0);
    __syncthreads();

    const int KT = NFPAD / 16;
    for (int kt = 0; kt < KT; kt++) {
        int cur = kt & 1, nxt = cur ^ 1;
        if (kt + 1 < KT) ldg((kt + 1) * 16);

        uint32_t af[2][4], bf[8][2];
        #pragma unroll
        for (int mi = 0; mi < 2; mi++) {
            int mr = arow + mi * 16 + g;
            af[mi][0] = As[cur][t4 * SA + mr];
            af[mi][1] = As[cur][t4 * SA + mr + 8];
            af[mi][2] = As[cur][(t4 + 4) * SA + mr];
            af[mi][3] = As[cur][(t4 + 4) * SA + mr + 8];
        }
        #pragma unroll
        for (int ni = 0; ni < 8; ni++) {
            int nc = bcol + ni * 8 + g;
            bf[ni][0] = Bs[cur][t4 * SB + nc];
            bf[ni][1] = Bs[cur][(t4 + 4) * SB + nc];
        }
        #pragma unroll
        for (int mi = 0; mi < 2; mi++)
            #pragma unroll
            for (int ni = 0; ni < 8; ni++)
                mma16(acc[mi][ni], af[mi], bf[ni]);

        if (kt + 1 < KT) sts(nxt);
        __syncthreads();
    }

    #pragma unroll
    for (int mi = 0; mi < 2; mi++) {
        int r = row0 + arow + mi * 16 + g;
        float b0 = bias[r], b1 = bias[r + 8];
        #pragma unroll
        for (int ni = 0; ni < 8; ni++) {
            int c = col0 + bcol + ni * 8 + t4 * 2;
            float2 v0, v1;
            v0.x = acc[mi][ni][0] + b0;
            v0.y = acc[mi][ni][1] + b0;
            v1.x = acc[mi][ni][2] + b1;
            v1.y = acc[mi][ni][3] + b1;
            *(float2*)&C[(size_t)r * PIX + c]       = v0;
            *(float2*)&C[(size_t)(r + 8) * PIX + c] = v1;
        }
    }
}

// ---------------- combine partial stats -> mx, inv ----------------
__global__ __launch_bounds__(256)
void combine_kernel(const float* __restrict__ pm, const float* __restrict__ ps,
                    float* __restrict__ mx, float* __restrict__ inv)
{
    int r = blockIdx.x * 256 + threadIdx.x;
    int b = blockIdx.y;
    float m = -1e30f;
    for (int cb = 0; cb < NBLK; cb++)
        m = fmaxf(m, pm[((size_t)b * NBLK + cb) * NTOK + r]);
    float s = 0.f;
    for (int cb = 0; cb < NBLK; cb++) {
        size_t idx = ((size_t)b * NBLK + cb) * NTOK + r;
        s += ps[idx] * __expf(pm[idx] - m);
    }
    mx[(size_t)b * NTOK + r]  = m;
    inv[(size_t)b * NTOK + r] = 1.f / s;
}

// ---------------- fp32 GEMM (proj 1x1) ----------------
__global__ __launch_bounds__(256)
void gemm128(const float* __restrict__ A, const float* __restrict__ Bm,
             float* __restrict__ Cm,
             int M, int Np, int K, int lda, int ldb, int ldc,
             float alpha, const float* __restrict__ bias,
             size_t sA, size_t sB, size_t sC)
{
    __shared__ float As[8][132];
    __shared__ float Bs[8][132];

    int bz = blockIdx.z;
    A  += (size_t)bz * sA;
    Bm += (size_t)bz * sB;
    Cm += (size_t)bz * sC;

    int tid = threadIdx.x;
    int tx = tid % 16;
    int ty = tid / 16;
    int row0 = blockIdx.y * 128;
    int col0 = blockIdx.x * 128;

    float acc[8][8];
    #pragma unroll
    for (int i = 0; i < 8; i++)
        #pragma unroll
        for (int j = 0; j < 8; j++) acc[i][j] = 0.f;

    int a_k = tid % 8;
    int a_m = (tid / 8) * 4;

    for (int k0 = 0; k0 < K; k0 += 8) {
        #pragma unroll
        for (int j = 0; j < 4; j++) {
            int m = a_m + j;
            int kk = k0 + a_k;
            float v = 0.f;
            if (row0 + m < M && kk < K) v = A[(size_t)(row0 + m) * lda + kk];
            As[a_k][m] = v;
        }
        {
            int b_n  = tid % 128;
            int b_kb = (tid / 128) * 4;
            #pragma unroll
            for (int j = 0; j < 4; j++) {
                int kk = k0 + b_kb + j;
                float v = 0.f;
                if (kk < K && col0 + b_n < Np) v = Bm[(size_t)kk * ldb + col0 + b_n];
                Bs[b_kb + j][b_n] = v;
            }
        }
        __syncthreads();

        #pragma unroll
        for (int kk = 0; kk < 8; kk++) {
            float a[8], b[8];
            #pragma unroll
            for (int i = 0; i < 8; i++) a[i] = As[kk][ty * 8 + i];
            #pragma unroll
            for (int j = 0; j < 8; j++) b[j] = Bs[kk][tx * 8 + j];
            #pragma unroll
            for (int i = 0; i < 8; i++)
                #pragma unroll
                for (int j = 0; j < 8; j++)
                    acc[i][j] += a[i] * b[j];
        }
        __syncthreads();
    }

    #pragma unroll
    for (int i = 0; i < 8; i++) {
        int m = row0 + ty * 8 + i;
        if (m >= M) continue;
        float bv = bias ? bias[m] : 0.f;
        #pragma unroll
        for (int j = 0; j < 8; j++) {
            int n = col0 + tx * 8 + j;
            if (n < Np) Cm[(size_t)m * ldc + n] = alpha * acc[i][j] + bv;
        }
    }
}

// ---------------- pad fuse weights ----------------
__global__ __launch_bounds__(256)
void copyw_kernel(const float* __restrict__ w, float* __restrict__ wp)
{
    int r = blockIdx.x;
    int k = threadIdx.x;
    wp[r * NFPAD + k] = (k < NFEAT) ? w[r * NFEAT + k] : 0.f;
}

// ---------------- reduce ----------------
__global__ __launch_bounds__(256)
void reduce_kernel(const float* __restrict__ fmap, const float* __restrict__ w,
                   const float* __restrict__ bias, float* __restrict__ xr)
{
    __shared__ float ws[INNER * C_DIM];
    int tid = threadIdx.x;
    for (int i = tid; i < INNER * C_DIM; i += 256) ws[i] = w[i];
    __syncthreads();

    int b = blockIdx.y;
    int p = blockIdx.x * 256 + tid;
    const float* fin = fmap + (size_t)b * C_DIM * PIX;
    float acc[INNER];
    #pragma unroll
    for (int o = 0; o < INNER; o++) acc[o] = 0.f;
    for (int ci = 0; ci < C_DIM; ci++) {
        float v = fin[(size_t)ci * PIX + p];
        #pragma unroll
        for (int o = 0; o < INNER; o++) acc[o] += ws[o * C_DIM + ci] * v;
    }
    float* xo = xr + (size_t)b * INNER * PIX;
    #pragma unroll
    for (int o = 0; o < INNER; o++) xo[(size_t)o * PIX + p] = acc[o] + bias[o];
}

// ---------------- dilated 3x3 conv ----------------
__global__ __launch_bounds__(256)
void dilconv_kernel(const float* __restrict__ xr, const float* __restrict__ dw,
                    const float* __restrict__ db, float* __restrict__ conv)
{
    __shared__ float ws[INNER * INNER * 9];
    int i = blockIdx.z;
    int d = i + 1;
    int b = blockIdx.y;
    int tid = threadIdx.x;
    for (int k = tid; k < INNER * INNER * 9; k += 256)
        ws[k] = dw[(size_t)i * INNER * INNER * 9 + k];
    __syncthreads();

    int p = blockIdx.x * 256 + tid;
    int h = p / HW, w = p % HW;
    const float* xin = xr + (size_t)b * INNER * PIX;
    float acc[INNER];
    #pragma unroll
    for (int co = 0; co < INNER; co++) acc[co] = 0.f;

    #pragma unroll
    for (int kh = 0; kh < 3; kh++) {
        int hh = h + (kh - 1) * d;
        if (hh < 0 || hh >= HW) continue;
        #pragma unroll
        for (int kw = 0; kw < 3; kw++) {
            int ww = w + (kw - 1) * d;
            if (ww < 0 || ww >= HW) continue;
            int q = hh * HW + ww;
            for (int ci = 0; ci < INNER; ci++) {
                float v = xin[(size_t)ci * PIX + q];
                int widx = ci * 9 + kh * 3 + kw;
                #pragma unroll
                for (int co = 0; co < INNER; co++)
                    acc[co] += ws[co * (INNER * 9) + widx] * v;
            }
        }
    }
    float* cout = conv + ((size_t)(i * BATCH + b) * INNER) * PIX;
    #pragma unroll
    for (int co = 0; co < INNER; co++)
        cout[(size_t)co * PIX + p] = acc[co] + db[i * INNER + co];
}

// ---------------- feats ----------------
__global__ __launch_bounds__(256)
void feats_kernel(const float* __restrict__ xr, const float* __restrict__ conv,
                  float* __restrict__ feats)
{
    int b = blockIdx.y;
    int p = blockIdx.x * 256 + threadIdx.x;
    int h = p / HW, w = p % HW;
    const float* xin = xr + (size_t)b * INNER * PIX;
    float* fo = feats + (size_t)b * NFPAD * PIX;

    int q[6];
    q[0] = p;
    q[1] = h * HW + (HW - 1 - w);
    q[2] = (HW - 1 - h) * HW + w;
    q[3] = w * HW + (HW - 1 - h);
    q[4] = (HW - 1 - h) * HW + (HW - 1 - w);
    q[5] = (HW - 1 - w) * HW + h;

    for (int c = 0; c < INNER; c++) {
        float cv[3];
        #pragma unroll
        for (int i = 0; i < 3; i++)
            cv[i] = conv[((size_t)(i * BATCH + b) * INNER + c) * PIX + p];
        float tv[6];
        #pragma unroll
        for (int t = 0; t < 6; t++)
            tv[t] = xin[(size_t)c * PIX + q[t]];
        #pragma unroll
        for (int i = 0; i < 3; i++)
            #pragma unroll
            for (int t = 0; t < 6; t++)
                fo[((size_t)((i * 6 + t) * INNER + c)) * PIX + p] = cv[i] * tv[t];
    }
    #pragma unroll
    for (int f = NFEAT; f < NFPAD; f++)
        fo[(size_t)f * PIX + p] = 0.f;
}

// ---------------- transpose: (b,c,p) -> (b,p,c) fp16 ----------------
__global__ __launch_bounds__(256)
void transpose_kernel(const float* __restrict__ src, __half* __restrict__ dst16)
{
    __shared__ float tile[32][33];
    int b = blockIdx.z;
    int p0 = blockIdx.x * 32, c0 = blockIdx.y * 32;
    const float* s = src + (size_t)b * C_DIM * PIX;
    __half* d16 = dst16 + (size_t)b * NTOK * C_DIM;
    int tx = threadIdx.x, ty = threadIdx.y;
    #pragma unroll
    for (int j = 0; j < 32; j += 8)
        tile[ty + j][tx] = s[(size_t)(c0 + ty + j) * PIX + p0 + tx];
    __syncthreads();
    #pragma unroll
    for (int j = 0; j < 32; j += 8)
        d16[(size_t)(p0 + ty + j) * C_DIM + c0 + tx] = __float2half(tile[tx][ty + j]);
}

// ---------------- final ----------------
__global__ __launch_bounds__(256)
void final_kernel(const float* __restrict__ fmap, const float* __restrict__ att,
                  float* __restrict__ out)
{
    __shared__ float tile[32][33];
    int b = blockIdx.z;
    int p0 = blockIdx.x * 32, c0 = blockIdx.y * 32;
    int tx = threadIdx.x, ty = threadIdx.y;
    const float* a = att + (size_t)b * NTOK * C_DIM;
    #pragma unroll
    for (int j = 0; j < 32; j += 8)
        tile[ty + j][tx] = a[(size_t)(p0 + ty + j) * C_DIM + c0 + tx];
    __syncthreads();
    const float* f = fmap + (size_t)b * C_DIM * PIX;
    float* o = out + (size_t)b * C_DIM * PIX;
    #pragma unroll
    for (int j = 0; j < 32; j += 8) {
        int c = c0 + ty + j, p = p0 + tx;
        o[(size_t)c * PIX + p] = f[(size_t)c * PIX + p] + 0.2f * tile[tx][ty + j];
    }
}

// ---------------- launch ----------------
extern "C" void kernel_launch(void* const* d_in, const int* in_sizes, int n_in,
                              void* d_out, int out_size)
{
    const float* x        = (const float*)d_in[0];
    const float* proj_w   = (const float*)d_in[1];
    const float* proj_b   = (const float*)d_in[2];
    const float* reduce_w = (const float*)d_in[3];
    const float* reduce_b = (const float*)d_in[4];
    const float* dil_w    = (const float*)d_in[5];
    const float* dil_b    = (const float*)d_in[6];
    const float* fuse_w   = (const float*)d_in[7];
    const float* fuse_b   = (const float*)d_in[8];
    float* out = (float*)d_out;

    void *p_fmap, *p_xr, *p_conv, *p_feats, *p_tokT, *p_tok16,
         *p_scores, *p_att, *p_mx, *p_inv, *p_fusew, *p_pm, *p_ps;
    cudaGetSymbolAddress(&p_fmap,   g_fmap);
    cudaGetSymbolAddress(&p_xr,     g_xr);
    cudaGetSymbolAddress(&p_conv,   g_conv);
    cudaGetSymbolAddress(&p_feats,  g_feats);
    cudaGetSymbolAddress(&p_tokT,   g_tokT);
    cudaGetSymbolAddress(&p_tok16,  g_tok16);
    cudaGetSymbolAddress(&p_scores, g_scores);
    cudaGetSymbolAddress(&p_att,    g_att);
    cudaGetSymbolAddress(&p_mx,     g_mx);
    cudaGetSymbolAddress(&p_inv,    g_inv);
    cudaGetSymbolAddress(&p_fusew,  g_fusew);
    cudaGetSymbolAddress(&p_pm,     g_pm);
    cudaGetSymbolAddress(&p_ps,     g_ps);

    float*  fmap   = (float*)p_fmap;
    float*  xr     = (float*)p_xr;
    float*  conv   = (float*)p_conv;
    float*  feats  = (float*)p_feats;
    float*  tokT   = (float*)p_tokT;
    __half* tok16  = (__half*)p_tok16;
    __half* scores = (__half*)p_scores;
    float*  att    = (float*)p_att;
    float*  mx     = (float*)p_mx;
    float*  inv    = (float*)p_inv;
    float*  fusew  = (float*)p_fusew;
    float*  pm     = (float*)p_pm;
    float*  ps     = (float*)p_ps;

    // 0) pad fuse weights
    copyw_kernel<<<C_DIM, 256>>>(fuse_w, fusew);

    // 1) proj 1x1 — fp32 (feeds residual directly)
    gemm128<<<dim3(PIX/128, C_DIM/128, BATCH), 256>>>(
        proj_w, x, fmap, C_DIM, PIX, C_DIM, C_DIM, PIX, PIX,
        1.f, proj_b, 0, (size_t)C_DIM*PIX, (size_t)C_DIM*PIX);

    // 2) reduce 1x1
    reduce_kernel<<<dim3(PIX/256, BATCH), 256>>>(fmap, reduce_w, reduce_b, xr);

    // 3) dilated convs
    dilconv_kernel<<<dim3(PIX/256, BATCH, 3), 256>>>(xr, dil_w, dil_b, conv);

    // 4) feats
    feats_kernel<<<dim3(PIX/256, BATCH), 256>>>(xr, conv, feats);

    // 5) fuse 1x1 — fp16 mma.sync
    gemm_f16_fuse<<<dim3(PIX/128, C_DIM/128, BATCH), 256>>>(
        fusew, feats, tokT, fuse_b);

    // 6) transpose -> tok16 (b,p,c) fp16 only
    transpose_kernel<<<dim3(PIX/32, C_DIM/32, BATCH), dim3(32, 8)>>>(tokT, tok16);

    // 7) scores (fp16 out) + fused softmax partial stats
    scores_f16<<<dim3(NBLK, NBLK, BATCH), 256>>>(tok16, scores, pm, ps);

    // 8) combine partials
    combine_kernel<<<dim3(NTOK/256, BATCH), 256>>>(pm, ps, mx, inv);

    // 9) att = softmax(scores) @ tok16 — exp fused into A load
    out_f16<<<dim3(1, NTOK/64, BATCH), 256>>>(scores, tok16, att, mx, inv);

    // 10) out = fmap + 0.2 * att^T
    final_kernel<<<dim3(PIX/32, C_DIM/32, BATCH), dim3(32, 8)>>>(fmap, att, out);
}